// round 11
// baseline (speedup 1.0000x reference)
#include <cuda_runtime.h>
#include <cuda_fp16.h>
#include <math.h>
#include <cstdint>

// ---------------------------------------------------------------------------
// Problem constants
// ---------------------------------------------------------------------------
#define NB   32
#define PP   1024
#define C0   64
#define KNN  16
#define NPTS (NB * PP)       // 32768
#define ROWS (NPTS * KNN)    // 524288
#define LRELU_ALPHA 0.1f
#define BN_EPS 1e-3f

// ---------------------------------------------------------------------------
// Static device scratch
// ---------------------------------------------------------------------------
__device__ __half d_Ah [NPTS * 128];     // features @ (W0[:64]-W0[64:])  (fp16)
__device__ __half d_Bh [NPTS * 128];     // features @ W0[64:]            (fp16)
__device__ float  d_SC [NPTS * 256];     // features @ Wsc (pre-BN, fp32)
__device__ __half d_y1 [ROWS * 128];     // y1 (pre-BN, fp16)
__device__ __half d_y2 [(size_t)ROWS * 256];  // y2 (pre-BN, fp16)
__device__ int    d_idx [ROWS];
__device__ uint32_t d_W1t[128 * 64];     // W1 as [n][kw] packed half2
__device__ uint32_t d_W2t[256 * 64];     // W2 as [n][kw] packed half2
__device__ float  d_sum  [4 * 256];
__device__ float  d_sumsq[4 * 256];

__device__ __forceinline__ void mma_f16(float* d, const uint32_t* a, const uint32_t* b) {
    asm volatile(
        "mma.sync.aligned.m16n8k16.row.col.f32.f16.f16.f32 "
        "{%0,%1,%2,%3}, {%4,%5,%6,%7}, {%8,%9}, {%0,%1,%2,%3};"
        : "+f"(d[0]), "+f"(d[1]), "+f"(d[2]), "+f"(d[3])
        : "r"(a[0]), "r"(a[1]), "r"(a[2]), "r"(a[3]), "r"(b[0]), "r"(b[1]));
}
__device__ __forceinline__ void ldmatrix_x4(uint32_t* r, uint32_t addr) {
    asm volatile("ldmatrix.sync.aligned.m8n8.x4.shared.b16 {%0,%1,%2,%3}, [%4];"
                 : "=r"(r[0]), "=r"(r[1]), "=r"(r[2]), "=r"(r[3]) : "r"(addr));
}
__device__ __forceinline__ uint32_t smem_u32(const void* p) {
    uint32_t a;
    asm("{ .reg .u64 t; cvta.to.shared.u64 t, %1; cvt.u32.u64 %0, t; }" : "=r"(a) : "l"(p));
    return a;
}
__device__ __forceinline__ uint32_t pack_h2(float lo, float hi) {
    __half2 h = __floats2half2_rn(lo, hi);
    return *(uint32_t*)&h;
}
__device__ __forceinline__ float lrelu(float x) {
    return x > 0.f ? x : LRELU_ALPHA * x;
}

// ---------------------------------------------------------------------------
// MEGA setup kernel: 1152 blocks x 256 thr.
//  blocks [0,128):    KNN (+ stats zero / W1t / W2t side duties on blocks 0-3)
//  blocks [128,640):  dual GEMM  A = f@(W0lo-W0hi) (sub<256) / B = f@W0hi
//  blocks [640,1152): shortcut GEMM SC = f@Wsc (two 128-col halves), fp32 out
// ---------------------------------------------------------------------------
__global__ void __launch_bounds__(256) mega_kernel(
    const float* __restrict__ pts, const float* __restrict__ feat,
    const float* __restrict__ W0,  const float* __restrict__ Wsc,
    const float* __restrict__ W1,  const float* __restrict__ W2) {
    __shared__ float sbuf[3072];   // knn: sx/sy/sz ; gemm: As(1024)+Bs(1024)
    const int bid = blockIdx.x;
    const int tid = threadIdx.x;

    if (bid < 128) {
        // ---- side duties -------------------------------------------------
        if (bid == 0) {
            for (int i = tid; i < 1024; i += 256) { d_sum[i] = 0.f; d_sumsq[i] = 0.f; }
        } else if (bid == 1) {
            for (int t = tid; t < 128 * 64; t += 256) {
                int n = t >> 6, kw = t & 63;
                d_W1t[t] = pack_h2(W1[(size_t)(2 * kw) * 128 + n],
                                   W1[(size_t)(2 * kw + 1) * 128 + n]);
            }
        } else if (bid <= 3) {
            int base = (bid - 2) * 8192;
            for (int i = tid; i < 8192; i += 256) {
                int t = base + i;
                int n = t >> 6, kw = t & 63;
                d_W2t[t] = pack_h2(W2[(size_t)(2 * kw) * 256 + n],
                                   W2[(size_t)(2 * kw + 1) * 256 + n]);
            }
        }
        // ---- knn ---------------------------------------------------------
        float* sx = sbuf;
        float* sy = sbuf + 1024;
        float* sz = sbuf + 2048;
        int n = bid >> 2;
        int p = ((bid & 3) << 8) + tid;
        const float* base = pts + (size_t)n * PP * 3;
        for (int i = tid; i < PP; i += 256) {
            sx[i] = base[i * 3 + 0];
            sy[i] = base[i * 3 + 1];
            sz[i] = base[i * 3 + 2];
        }
        __syncthreads();
        float qx = sx[p], qy = sy[p], qz = sz[p];
        float bd[KNN]; int bi[KNN];
#pragma unroll
        for (int i = 0; i < KNN; i++) { bd[i] = 3.0e38f; bi[i] = 0; }
        for (int q = 0; q < PP; q++) {
            float dx = sx[q] - qx, dy = sy[q] - qy, dz = sz[q] - qz;
            float d = dx * dx + dy * dy + dz * dz;
            if (q == p) continue;
            if (d < bd[KNN - 1]) {
                int j = KNN - 1;
                while (j > 0 && bd[j - 1] > d) { bd[j] = bd[j - 1]; bi[j] = bi[j - 1]; j--; }
                bd[j] = d; bi[j] = q;
            }
        }
        int ob = (n * PP + p) * KNN;
        for (int k = 0; k < KNN; k++) d_idx[ob + k] = bi[k];
        return;
    }

    // ---- GEMM branches (Kc=64) ------------------------------------------
    const bool dual = bid < 640;
    const int sub = dual ? bid - 128 : bid - 640;
    const int rowBlock = sub & 255;
    const int ysel = sub >> 8;          // dual: 0=A,1=B ; SC: col half
    float* As = sbuf;                   // [8][128]
    float* Bs = sbuf + 1024;            // [8][128]
    const int rowBase = rowBlock * 128;
    const int tx = tid & 15, ty = tid >> 4;
    float acc[8][8];
#pragma unroll
    for (int i = 0; i < 8; i++)
#pragma unroll
        for (int j = 0; j < 8; j++) acc[i][j] = 0.f;
    const int a_row = tid >> 1, a_k4 = (tid & 1) * 4;
    const int b_k = tid >> 5, b_n = (tid & 31) * 4;
#pragma unroll
    for (int k0 = 0; k0 < 64; k0 += 8) {
        float4 av = *(const float4*)&feat[(size_t)(rowBase + a_row) * 64 + k0 + a_k4];
        As[(a_k4 + 0) * 128 + a_row] = av.x;
        As[(a_k4 + 1) * 128 + a_row] = av.y;
        As[(a_k4 + 2) * 128 + a_row] = av.z;
        As[(a_k4 + 3) * 128 + a_row] = av.w;
        float4 bv;
        if (dual) {
            float4 bhi = *(const float4*)&W0[(size_t)(64 + k0 + b_k) * 128 + b_n];
            if (ysel == 0) {
                float4 blo = *(const float4*)&W0[(size_t)(k0 + b_k) * 128 + b_n];
                bv.x = blo.x - bhi.x; bv.y = blo.y - bhi.y;
                bv.z = blo.z - bhi.z; bv.w = blo.w - bhi.w;
            } else bv = bhi;
        } else {
            bv = *(const float4*)&Wsc[(size_t)(k0 + b_k) * 256 + ysel * 128 + b_n];
        }
        *(float4*)&Bs[b_k * 128 + b_n] = bv;
        __syncthreads();
#pragma unroll
        for (int kk = 0; kk < 8; kk++) {
            float4 a0 = *(const float4*)&As[kk * 128 + ty * 8];
            float4 a1 = *(const float4*)&As[kk * 128 + ty * 8 + 4];
            float4 b0 = *(const float4*)&Bs[kk * 128 + tx * 8];
            float4 b1 = *(const float4*)&Bs[kk * 128 + tx * 8 + 4];
            float a[8] = {a0.x, a0.y, a0.z, a0.w, a1.x, a1.y, a1.z, a1.w};
            float b[8] = {b0.x, b0.y, b0.z, b0.w, b1.x, b1.y, b1.z, b1.w};
#pragma unroll
            for (int i = 0; i < 8; i++)
#pragma unroll
                for (int j = 0; j < 8; j++) acc[i][j] += a[i] * b[j];
        }
        __syncthreads();
    }
    if (dual) {
        __half* Yh = ysel ? d_Bh : d_Ah;
#pragma unroll
        for (int i = 0; i < 8; i++) {
            int row = rowBase + ty * 8 + i;
            uint4 v;
            v.x = pack_h2(acc[i][0], acc[i][1]);
            v.y = pack_h2(acc[i][2], acc[i][3]);
            v.z = pack_h2(acc[i][4], acc[i][5]);
            v.w = pack_h2(acc[i][6], acc[i][7]);
            *(uint4*)&Yh[(size_t)row * 128 + tx * 8] = v;
        }
    } else {
#pragma unroll
        for (int i = 0; i < 8; i++) {
            int row = rowBase + ty * 8 + i;
            float4 c0 = {acc[i][0], acc[i][1], acc[i][2], acc[i][3]};
            float4 c1 = {acc[i][4], acc[i][5], acc[i][6], acc[i][7]};
            *(float4*)&d_SC[(size_t)row * 256 + ysel * 128 + tx * 8]     = c0;
            *(float4*)&d_SC[(size_t)row * 256 + ysel * 128 + tx * 8 + 4] = c1;
        }
    }
}

// ---------------------------------------------------------------------------
// Stats kernel: blocks [0,2048) layer-0 virtual-y0 stats (fp16 A/B + idx);
//               blocks [2048,2560) shortcut SC stats (layer 3).
// ---------------------------------------------------------------------------
__global__ void __launch_bounds__(256) stats_kernel() {
    if (blockIdx.x < 2048) {
        const uint4* A4 = (const uint4*)d_Ah;
        const uint4* B4 = (const uint4*)d_Bh;
        __shared__ float ssum[128], ssq[128];
        if (threadIdx.x < 128) { ssum[threadIdx.x] = 0.f; ssq[threadIdx.x] = 0.f; }
        __syncthreads();
        const int start = blockIdx.x * 256 + threadIdx.x;
        const int c8 = start & 15;
        float s[8], q[8];
#pragma unroll
        for (int j = 0; j < 8; j++) { s[j] = 0.f; q[j] = 0.f; }
#pragma unroll 4
        for (int i = 0; i < 16; i++) {
            int e = start + i * 524288;
            int r = e >> 4, cc = e & 15;
            int np = r >> 4, n = r >> 14;
            int id = __ldg(&d_idx[r]);
            uint4 a = A4[(size_t)np * 16 + cc];
            uint4 b = B4[((size_t)n * 1024 + id) * 16 + cc];
            uint32_t aw[4] = {a.x, a.y, a.z, a.w};
            uint32_t bw[4] = {b.x, b.y, b.z, b.w};
#pragma unroll
            for (int j = 0; j < 4; j++) {
                float2 fa = __half22float2(*(__half2*)&aw[j]);
                float2 fb = __half22float2(*(__half2*)&bw[j]);
                float y0 = fa.x + fb.x, y1 = fa.y + fb.y;
                s[j * 2]     += y0; q[j * 2]     += y0 * y0;
                s[j * 2 + 1] += y1; q[j * 2 + 1] += y1 * y1;
            }
        }
#pragma unroll
        for (int j = 0; j < 8; j++) {
            atomicAdd(&ssum[c8 * 8 + j], s[j]);
            atomicAdd(&ssq [c8 * 8 + j], q[j]);
        }
        __syncthreads();
        if (threadIdx.x < 128) {
            atomicAdd(&d_sum  [threadIdx.x], ssum[threadIdx.x]);
            atomicAdd(&d_sumsq[threadIdx.x], ssq[threadIdx.x]);
        }
    } else {
        int b = blockIdx.x - 2048;            // 0..511 -> 64 rows each
        int c = threadIdx.x;                  // channel
        const float* base = d_SC + (size_t)b * 64 * 256 + c;
        float s = 0.f, q = 0.f;
#pragma unroll 8
        for (int r = 0; r < 64; r++) {
            float v = base[(size_t)r * 256];
            s += v; q += v * v;
        }
        atomicAdd(&d_sum  [3 * 256 + c], s);
        atomicAdd(&d_sumsq[3 * 256 + c], q);
    }
}

// ---------------------------------------------------------------------------
// fp16 mma GEMM with ldmatrix: BM=128, K=128 one-shot, 256 thr (8 warps 4x2),
// occ 2. N_TOT/128 column halves processed serially, A produced ONCE.
// Epilogue: C staged into the just-consumed Bs half (same 128xKW footprint),
// then streamed out as coalesced uint4 with BN stats computed inline.
// MODE 0: A = lrelu(BN0(gather Ah+Bh)), Y = y1 [ROWS,128]
// MODE 1: A = lrelu(BN1(y1)),           Y = y2 [ROWS,256]
// ---------------------------------------------------------------------------
#define KW 68
template <int N_TOT, int MODE>
__global__ void __launch_bounds__(256, 2) gemm_mma_kernel(
    const __half* __restrict__ Xin, const uint32_t* __restrict__ Wt,
    __half* __restrict__ Y, const float* __restrict__ g, const float* __restrict__ b) {
    constexpr int LAYER_IN  = MODE;
    constexpr int LAYER_OUT = MODE + 1;
    constexpr int NH = N_TOT / 128;
    extern __shared__ char smem_raw[];
    uint32_t* As = (uint32_t*)smem_raw;                    // [128][KW]
    uint32_t* Bs = As + 128 * KW;                          // [N_TOT][KW]
    float*  ssum = (float*)(Bs + N_TOT * KW);              // [N_TOT]
    float*  ssq  = ssum + N_TOT;                           // [N_TOT]
    float*  scs  = ssq + N_TOT;                            // [128]
    float*  shs  = scs + 128;                              // [128]

    const int tid = threadIdx.x;
    const int wid = tid >> 5;
    const int lane = tid & 31;
    const int gid = lane >> 2;
    const int tg  = lane & 3;
    const int warpRow = wid & 3;
    const int warpCol = wid >> 2;
    const int tileBase = blockIdx.x * 128;

    // inline finalize of BN(layer_in)
    if (tid < 128) {
        float mean = d_sum[LAYER_IN * 256 + tid] * (1.0f / (float)ROWS);
        float var  = d_sumsq[LAYER_IN * 256 + tid] * (1.0f / (float)ROWS) - mean * mean;
        float sc = g[tid] * rsqrtf(var + BN_EPS);
        scs[tid] = sc;
        shs[tid] = b[tid] - mean * sc;
    }
    for (int c2 = tid; c2 < N_TOT; c2 += 256) { ssum[c2] = 0.f; ssq[c2] = 0.f; }
    __syncthreads();

    // ---- B tile: packed copy from pre-transposed Wt ------------------------
    {
        const uint4* src = (const uint4*)Wt;
#pragma unroll
        for (int i = 0; i < N_TOT / 16; i++) {
            int e4 = tid + i * 256;
            int n = e4 >> 4, kw4 = e4 & 15;
            *(uint4*)&Bs[n * KW + kw4 * 4] = src[e4];
        }
    }

    // ---- A tile (fused gather/BN/lrelu producer, fp16 inputs) --------------
    int ids[8];
    if (MODE == 0) {
#pragma unroll
        for (int i = 0; i < 8; i++) {
            int r = (tid + i * 256) >> 4;
            ids[i] = __ldg(&d_idx[tileBase + r]);
        }
    }
#pragma unroll
    for (int i = 0; i < 8; i++) {
        int e = tid + i * 256;
        int r = e >> 4, cw = e & 15;
        int R = tileBase + r;
        float x[8];
        if (MODE == 0) {
            int np = R >> 4, n = R >> 14;
            uint4 ha = ((const uint4*)d_Ah)[(size_t)np * 16 + cw];
            uint4 hb = ((const uint4*)d_Bh)[((size_t)n * 1024 + ids[i]) * 16 + cw];
            uint32_t aw[4] = {ha.x, ha.y, ha.z, ha.w};
            uint32_t bw[4] = {hb.x, hb.y, hb.z, hb.w};
#pragma unroll
            for (int j = 0; j < 4; j++) {
                float2 fa = __half22float2(*(__half2*)&aw[j]);
                float2 fb = __half22float2(*(__half2*)&bw[j]);
                x[j * 2] = fa.x + fb.x; x[j * 2 + 1] = fa.y + fb.y;
            }
        } else {
            uint4 h = ((const uint4*)&Xin[(size_t)R * 128])[cw];
            uint32_t hw[4] = {h.x, h.y, h.z, h.w};
#pragma unroll
            for (int j = 0; j < 4; j++) {
                float2 f = __half22float2(*(__half2*)&hw[j]);
                x[j * 2] = f.x; x[j * 2 + 1] = f.y;
            }
        }
        const float* sc = &scs[cw * 8];
        const float* sh = &shs[cw * 8];
        float y[8];
#pragma unroll
        for (int j = 0; j < 8; j++) y[j] = lrelu(x[j] * sc[j] + sh[j]);
        uint4 v;
        v.x = pack_h2(y[0], y[1]); v.y = pack_h2(y[2], y[3]);
        v.z = pack_h2(y[4], y[5]); v.w = pack_h2(y[6], y[7]);
        *(uint4*)&As[r * KW + cw * 4] = v;
    }
    __syncthreads();

    // ---- ldmatrix base addresses (k-step 0), advance 32B per k-step --------
    const int t8 = lane >> 3, r8 = lane & 7;
    uint32_t aAddr[2], bAddr[4];
#pragma unroll
    for (int mi = 0; mi < 2; mi++) {
        int row = warpRow * 32 + mi * 16 + (t8 & 1) * 8 + r8;
        aAddr[mi] = smem_u32(&As[row * KW + (t8 >> 1) * 4]);
    }
#pragma unroll
    for (int nj = 0; nj < 4; nj++) {
        int row = warpCol * 64 + nj * 16 + (t8 >> 1) * 8 + r8;
        bAddr[nj] = smem_u32(&Bs[row * KW + (t8 & 1) * 4]);
    }

    // ---- loop over N halves: MMA + staged epilogue -------------------------
    const int c4 = tid & 15;
#pragma unroll
    for (int h = 0; h < NH; h++) {
        const uint32_t bOff = (uint32_t)h * 128u * KW * 4u;
        float c[2][8][4];
#pragma unroll
        for (int mi = 0; mi < 2; mi++)
#pragma unroll
            for (int ni = 0; ni < 8; ni++)
#pragma unroll
                for (int j = 0; j < 4; j++) c[mi][ni][j] = 0.f;

#pragma unroll
        for (int k0 = 0; k0 < 8; k0++) {
            uint32_t af[2][4], bf[4][4];
#pragma unroll
            for (int mi = 0; mi < 2; mi++) ldmatrix_x4(af[mi], aAddr[mi] + k0 * 32);
#pragma unroll
            for (int nj = 0; nj < 4; nj++) ldmatrix_x4(bf[nj], bAddr[nj] + bOff + k0 * 32);
#pragma unroll
            for (int mi = 0; mi < 2; mi++)
#pragma unroll
                for (int nj = 0; nj < 4; nj++) {
                    mma_f16(c[mi][nj * 2],     af[mi], &bf[nj][0]);
                    mma_f16(c[mi][nj * 2 + 1], af[mi], &bf[nj][2]);
                }
        }

        // ---- stage C tile into the just-consumed Bs half -------------------
        __syncthreads();                         // all warps done reading Bs[h]
        uint32_t* Cs = Bs + h * 128 * KW;        // [128][KW], stride 68 words
#pragma unroll
        for (int mi = 0; mi < 2; mi++) {
            int r0 = warpRow * 32 + mi * 16 + gid;
#pragma unroll
            for (int ni = 0; ni < 8; ni++) {
                int w = warpCol * 32 + ni * 4 + tg;      // col word in half
                Cs[ r0      * KW + w] = pack_h2(c[mi][ni][0], c[mi][ni][1]);
                Cs[(r0 + 8) * KW + w] = pack_h2(c[mi][ni][2], c[mi][ni][3]);
            }
        }
        __syncthreads();

        // ---- coalesced uint4 stream-out + inline BN stats ------------------
        float s[8], q[8];
#pragma unroll
        for (int j = 0; j < 8; j++) { s[j] = 0.f; q[j] = 0.f; }
#pragma unroll
        for (int i = 0; i < 8; i++) {
            int e = tid + i * 256;
            int row = e >> 4;                     // c4 = e & 15 (fixed per thread)
            uint4 v = *(uint4*)&Cs[row * KW + c4 * 4];
            *(uint4*)&Y[(size_t)(tileBase + row) * N_TOT + h * 128 + c4 * 8] = v;
            uint32_t wv[4] = {v.x, v.y, v.z, v.w};
#pragma unroll
            for (int j = 0; j < 4; j++) {
                float2 f = __half22float2(*(__half2*)&wv[j]);
                s[j * 2]     += f.x; q[j * 2]     += f.x * f.x;
                s[j * 2 + 1] += f.y; q[j * 2 + 1] += f.y * f.y;
            }
        }
#pragma unroll
        for (int j = 0; j < 8; j++) {
            atomicAdd(&ssum[h * 128 + c4 * 8 + j], s[j]);
            atomicAdd(&ssq [h * 128 + c4 * 8 + j], q[j]);
        }
    }
    __syncthreads();
    for (int c2 = tid; c2 < N_TOT; c2 += 256) {
        atomicAdd(&d_sum  [LAYER_OUT * 256 + c2], ssum[c2]);
        atomicAdd(&d_sumsq[LAYER_OUT * 256 + c2], ssq[c2]);
    }
}

// ---------------------------------------------------------------------------
// Final epilogue with inline finalize of BN2 (layer 2) and BN_sc (layer 3):
// out = lrelu( BN_sc(SC) + mean_k lrelu(BN2(y2)) )
// ---------------------------------------------------------------------------
__global__ void __launch_bounds__(256) final_kernel(
    float* __restrict__ out,
    const float* __restrict__ g2, const float* __restrict__ b2,
    const float* __restrict__ gsc, const float* __restrict__ bsc) {
    __shared__ float s2s[256], h2s[256], s3s[256], h3s[256];
    {
        int c = threadIdx.x;
        float mean2 = d_sum[2 * 256 + c] * (1.0f / (float)ROWS);
        float var2  = d_sumsq[2 * 256 + c] * (1.0f / (float)ROWS) - mean2 * mean2;
        float sc2 = g2[c] * rsqrtf(var2 + BN_EPS);
        s2s[c] = sc2; h2s[c] = b2[c] - mean2 * sc2;
        float mean3 = d_sum[3 * 256 + c] * (1.0f / (float)NPTS);
        float var3  = d_sumsq[3 * 256 + c] * (1.0f / (float)NPTS) - mean3 * mean3;
        float sc3 = gsc[c] * rsqrtf(var3 + BN_EPS);
        s3s[c] = sc3; h3s[c] = bsc[c] - mean3 * sc3;
    }
    __syncthreads();
    int t = blockIdx.x * blockDim.x + threadIdx.x;
    int np = t >> 6, c4 = t & 63;
    float4 s2 = *(const float4*)&s2s[c4 * 4];
    float4 h2 = *(const float4*)&h2s[c4 * 4];
    float4 s3 = *(const float4*)&s3s[c4 * 4];
    float4 h3 = *(const float4*)&h3s[c4 * 4];
    const uint2* Y2 = (const uint2*)d_y2;
    size_t base = (size_t)np * 16 * 64 + c4;
    float ax = 0, ay = 0, az = 0, aw = 0;
#pragma unroll
    for (int k = 0; k < KNN; k++) {
        uint2 hv = Y2[base + (size_t)k * 64];
        float2 f01 = __half22float2(*(__half2*)&hv.x);
        float2 f23 = __half22float2(*(__half2*)&hv.y);
        ax += lrelu(f01.x * s2.x + h2.x);
        ay += lrelu(f01.y * s2.y + h2.y);
        az += lrelu(f23.x * s2.z + h2.z);
        aw += lrelu(f23.y * s2.w + h2.w);
    }
    const float inv = 1.0f / (float)KNN;
    float4 s = ((const float4*)d_SC)[np * 64 + c4];
    float4 o;
    o.x = lrelu(s.x * s3.x + h3.x + ax * inv);
    o.y = lrelu(s.y * s3.y + h3.y + ay * inv);
    o.z = lrelu(s.z * s3.z + h3.z + az * inv);
    o.w = lrelu(s.w * s3.w + h3.w + aw * inv);
    ((float4*)out)[t] = o;
}

// ---------------------------------------------------------------------------
// Launch (5 launches; mma2 at idx 3 -> ncu abs index 5 gets profiled)
// ---------------------------------------------------------------------------
extern "C" void kernel_launch(void* const* d_in, const int* in_sizes, int n_in,
                              void* d_out, int out_size) {
    const float* points   = (const float*)d_in[0];
    const float* features = (const float*)d_in[1];
    const float* W0  = (const float*)d_in[2];
    const float* g0  = (const float*)d_in[3];
    const float* b0  = (const float*)d_in[4];
    const float* W1  = (const float*)d_in[5];
    const float* g1  = (const float*)d_in[6];
    const float* b1  = (const float*)d_in[7];
    const float* W2  = (const float*)d_in[8];
    const float* g2  = (const float*)d_in[9];
    const float* b2  = (const float*)d_in[10];
    const float* Wsc = (const float*)d_in[11];
    const float* gsc = (const float*)d_in[12];
    const float* bsc = (const float*)d_in[13];
    float* out = (float*)d_out;

    __half *p1, *p2;
    uint32_t *pW1t, *pW2t;
    cudaGetSymbolAddress((void**)&p1,  d_y1);
    cudaGetSymbolAddress((void**)&p2,  d_y2);
    cudaGetSymbolAddress((void**)&pW1t, d_W1t);
    cudaGetSymbolAddress((void**)&pW2t, d_W2t);

    constexpr int SMEM_MMA1 = (128 * KW + 128 * KW) * 4 + (2 * 128 + 2 * 128) * 4;
    constexpr int SMEM_MMA2 = (128 * KW + 256 * KW) * 4 + (2 * 256 + 2 * 128) * 4;
    cudaFuncSetAttribute(gemm_mma_kernel<128, 0>,
                         cudaFuncAttributeMaxDynamicSharedMemorySize, SMEM_MMA1);
    cudaFuncSetAttribute(gemm_mma_kernel<256, 1>,
                         cudaFuncAttributeMaxDynamicSharedMemorySize, SMEM_MMA2);

    // 0: mega setup (knn + stats zero + W transposes + dual GEMM + SC GEMM)
    mega_kernel<<<1152, 256>>>(points, features, W0, Wsc, W1, W2);
    // 1: layer-0 virtual-y0 stats + SC stats
    stats_kernel<<<2560, 256>>>();
    // 2: layer-1 MMA (gather+BN0+lrelu fused; BN0 finalize inline)
    gemm_mma_kernel<128, 0><<<ROWS / 128, 256, SMEM_MMA1>>>(nullptr, pW1t, p1, g0, b0);
    // 3: layer-2 MMA (BN1+lrelu fused; both N-halves, A produced once) [PROFILED]
    gemm_mma_kernel<256, 1><<<ROWS / 128, 256, SMEM_MMA2>>>(p1, pW2t, p2, g1, b1);
    // 4: final epilogue (BN2 + BN_sc finalize inline)
    final_kernel<<<NPTS * 64 / 256, 256>>>(out, g2, b2, gsc, bsc);
}

// round 13
// speedup vs baseline: 1.0127x; 1.0127x over previous
#include <cuda_runtime.h>
#include <cuda_fp16.h>
#include <math.h>
#include <cstdint>

// ---------------------------------------------------------------------------
// Problem constants
// ---------------------------------------------------------------------------
#define NB   32
#define PP   1024
#define C0   64
#define KNN  16
#define NPTS (NB * PP)       // 32768
#define ROWS (NPTS * KNN)    // 524288
#define LRELU_ALPHA 0.1f
#define BN_EPS 1e-3f

// ---------------------------------------------------------------------------
// Static device scratch
// ---------------------------------------------------------------------------
__device__ __half d_Ah [NPTS * 128];     // features @ (W0[:64]-W0[64:])  (fp16)
__device__ __half d_Bh [NPTS * 128];     // features @ W0[64:]            (fp16)
__device__ float  d_SC [NPTS * 256];     // features @ Wsc (pre-BN, fp32)
__device__ __half d_y1 [ROWS * 128];     // y1 (pre-BN, fp16)
__device__ __half d_y2 [(size_t)ROWS * 256];  // y2 (pre-BN, fp16)
__device__ int    d_idx [ROWS];
__device__ uint32_t d_W1t[128 * 64];     // W1 as [n][kw] packed half2
__device__ uint32_t d_W2t[256 * 64];     // W2 as [n][kw] packed half2
__device__ float  d_sum  [4 * 256];
__device__ float  d_sumsq[4 * 256];

__device__ __forceinline__ void mma_f16(float* d, const uint32_t* a, const uint32_t* b) {
    asm volatile(
        "mma.sync.aligned.m16n8k16.row.col.f32.f16.f16.f32 "
        "{%0,%1,%2,%3}, {%4,%5,%6,%7}, {%8,%9}, {%0,%1,%2,%3};"
        : "+f"(d[0]), "+f"(d[1]), "+f"(d[2]), "+f"(d[3])
        : "r"(a[0]), "r"(a[1]), "r"(a[2]), "r"(a[3]), "r"(b[0]), "r"(b[1]));
}
__device__ __forceinline__ void ldmatrix_x4(uint32_t* r, uint32_t addr) {
    asm volatile("ldmatrix.sync.aligned.m8n8.x4.shared.b16 {%0,%1,%2,%3}, [%4];"
                 : "=r"(r[0]), "=r"(r[1]), "=r"(r[2]), "=r"(r[3]) : "r"(addr));
}
__device__ __forceinline__ uint32_t smem_u32(const void* p) {
    uint32_t a;
    asm("{ .reg .u64 t; cvta.to.shared.u64 t, %1; cvt.u32.u64 %0, t; }" : "=r"(a) : "l"(p));
    return a;
}
__device__ __forceinline__ uint32_t pack_h2(float lo, float hi) {
    __half2 h = __floats2half2_rn(lo, hi);
    return *(uint32_t*)&h;
}
__device__ __forceinline__ float lrelu(float x) {
    return x > 0.f ? x : LRELU_ALPHA * x;
}

// ---------------------------------------------------------------------------
// MEGA setup kernel: 1152 blocks x 256 thr.
//  blocks [0,128):    KNN (+ stats zero / W1t / W2t side duties on blocks 0-3)
//  blocks [128,640):  dual GEMM  A = f@(W0lo-W0hi) (sub<256) / B = f@W0hi
//  blocks [640,1152): shortcut GEMM SC = f@Wsc (two 128-col halves), fp32 out
// ---------------------------------------------------------------------------
__global__ void __launch_bounds__(256) mega_kernel(
    const float* __restrict__ pts, const float* __restrict__ feat,
    const float* __restrict__ W0,  const float* __restrict__ Wsc,
    const float* __restrict__ W1,  const float* __restrict__ W2) {
    __shared__ float sbuf[3072];   // knn: sx/sy/sz ; gemm: As(1024)+Bs(1024)
    const int bid = blockIdx.x;
    const int tid = threadIdx.x;

    if (bid < 128) {
        // ---- side duties -------------------------------------------------
        if (bid == 0) {
            for (int i = tid; i < 1024; i += 256) { d_sum[i] = 0.f; d_sumsq[i] = 0.f; }
        } else if (bid == 1) {
            for (int t = tid; t < 128 * 64; t += 256) {
                int n = t >> 6, kw = t & 63;
                d_W1t[t] = pack_h2(W1[(size_t)(2 * kw) * 128 + n],
                                   W1[(size_t)(2 * kw + 1) * 128 + n]);
            }
        } else if (bid <= 3) {
            int base = (bid - 2) * 8192;
            for (int i = tid; i < 8192; i += 256) {
                int t = base + i;
                int n = t >> 6, kw = t & 63;
                d_W2t[t] = pack_h2(W2[(size_t)(2 * kw) * 256 + n],
                                   W2[(size_t)(2 * kw + 1) * 256 + n]);
            }
        }
        // ---- knn ---------------------------------------------------------
        float* sx = sbuf;
        float* sy = sbuf + 1024;
        float* sz = sbuf + 2048;
        int n = bid >> 2;
        int p = ((bid & 3) << 8) + tid;
        const float* base = pts + (size_t)n * PP * 3;
        for (int i = tid; i < PP; i += 256) {
            sx[i] = base[i * 3 + 0];
            sy[i] = base[i * 3 + 1];
            sz[i] = base[i * 3 + 2];
        }
        __syncthreads();
        float qx = sx[p], qy = sy[p], qz = sz[p];
        float bd[KNN]; int bi[KNN];
#pragma unroll
        for (int i = 0; i < KNN; i++) { bd[i] = 3.0e38f; bi[i] = 0; }
        for (int q = 0; q < PP; q++) {
            float dx = sx[q] - qx, dy = sy[q] - qy, dz = sz[q] - qz;
            float d = dx * dx + dy * dy + dz * dz;
            if (q == p) continue;
            if (d < bd[KNN - 1]) {
                int j = KNN - 1;
                while (j > 0 && bd[j - 1] > d) { bd[j] = bd[j - 1]; bi[j] = bi[j - 1]; j--; }
                bd[j] = d; bi[j] = q;
            }
        }
        int ob = (n * PP + p) * KNN;
        for (int k = 0; k < KNN; k++) d_idx[ob + k] = bi[k];
        return;
    }

    // ---- GEMM branches (Kc=64) ------------------------------------------
    const bool dual = bid < 640;
    const int sub = dual ? bid - 128 : bid - 640;
    const int rowBlock = sub & 255;
    const int ysel = sub >> 8;          // dual: 0=A,1=B ; SC: col half
    float* As = sbuf;                   // [8][128]
    float* Bs = sbuf + 1024;            // [8][128]
    const int rowBase = rowBlock * 128;
    const int tx = tid & 15, ty = tid >> 4;
    float acc[8][8];
#pragma unroll
    for (int i = 0; i < 8; i++)
#pragma unroll
        for (int j = 0; j < 8; j++) acc[i][j] = 0.f;
    const int a_row = tid >> 1, a_k4 = (tid & 1) * 4;
    const int b_k = tid >> 5, b_n = (tid & 31) * 4;
#pragma unroll
    for (int k0 = 0; k0 < 64; k0 += 8) {
        float4 av = *(const float4*)&feat[(size_t)(rowBase + a_row) * 64 + k0 + a_k4];
        As[(a_k4 + 0) * 128 + a_row] = av.x;
        As[(a_k4 + 1) * 128 + a_row] = av.y;
        As[(a_k4 + 2) * 128 + a_row] = av.z;
        As[(a_k4 + 3) * 128 + a_row] = av.w;
        float4 bv;
        if (dual) {
            float4 bhi = *(const float4*)&W0[(size_t)(64 + k0 + b_k) * 128 + b_n];
            if (ysel == 0) {
                float4 blo = *(const float4*)&W0[(size_t)(k0 + b_k) * 128 + b_n];
                bv.x = blo.x - bhi.x; bv.y = blo.y - bhi.y;
                bv.z = blo.z - bhi.z; bv.w = blo.w - bhi.w;
            } else bv = bhi;
        } else {
            bv = *(const float4*)&Wsc[(size_t)(k0 + b_k) * 256 + ysel * 128 + b_n];
        }
        *(float4*)&Bs[b_k * 128 + b_n] = bv;
        __syncthreads();
#pragma unroll
        for (int kk = 0; kk < 8; kk++) {
            float4 a0 = *(const float4*)&As[kk * 128 + ty * 8];
            float4 a1 = *(const float4*)&As[kk * 128 + ty * 8 + 4];
            float4 b0 = *(const float4*)&Bs[kk * 128 + tx * 8];
            float4 b1 = *(const float4*)&Bs[kk * 128 + tx * 8 + 4];
            float a[8] = {a0.x, a0.y, a0.z, a0.w, a1.x, a1.y, a1.z, a1.w};
            float b[8] = {b0.x, b0.y, b0.z, b0.w, b1.x, b1.y, b1.z, b1.w};
#pragma unroll
            for (int i = 0; i < 8; i++)
#pragma unroll
                for (int j = 0; j < 8; j++) acc[i][j] += a[i] * b[j];
        }
        __syncthreads();
    }
    if (dual) {
        __half* Yh = ysel ? d_Bh : d_Ah;
#pragma unroll
        for (int i = 0; i < 8; i++) {
            int row = rowBase + ty * 8 + i;
            uint4 v;
            v.x = pack_h2(acc[i][0], acc[i][1]);
            v.y = pack_h2(acc[i][2], acc[i][3]);
            v.z = pack_h2(acc[i][4], acc[i][5]);
            v.w = pack_h2(acc[i][6], acc[i][7]);
            *(uint4*)&Yh[(size_t)row * 128 + tx * 8] = v;
        }
    } else {
#pragma unroll
        for (int i = 0; i < 8; i++) {
            int row = rowBase + ty * 8 + i;
            float4 c0 = {acc[i][0], acc[i][1], acc[i][2], acc[i][3]};
            float4 c1 = {acc[i][4], acc[i][5], acc[i][6], acc[i][7]};
            *(float4*)&d_SC[(size_t)row * 256 + ysel * 128 + tx * 8]     = c0;
            *(float4*)&d_SC[(size_t)row * 256 + ysel * 128 + tx * 8 + 4] = c1;
        }
    }
}

// ---------------------------------------------------------------------------
// Stats kernel: blocks [0,2048) layer-0 virtual-y0 stats (fp16 A/B + idx);
//               blocks [2048,2560) shortcut SC stats (layer 3).
// ---------------------------------------------------------------------------
__global__ void __launch_bounds__(256) stats_kernel() {
    if (blockIdx.x < 2048) {
        const uint4* A4 = (const uint4*)d_Ah;
        const uint4* B4 = (const uint4*)d_Bh;
        __shared__ float ssum[128], ssq[128];
        if (threadIdx.x < 128) { ssum[threadIdx.x] = 0.f; ssq[threadIdx.x] = 0.f; }
        __syncthreads();
        const int start = blockIdx.x * 256 + threadIdx.x;
        const int c8 = start & 15;
        float s[8], q[8];
#pragma unroll
        for (int j = 0; j < 8; j++) { s[j] = 0.f; q[j] = 0.f; }
#pragma unroll 4
        for (int i = 0; i < 16; i++) {
            int e = start + i * 524288;
            int r = e >> 4, cc = e & 15;
            int np = r >> 4, n = r >> 14;
            int id = __ldg(&d_idx[r]);
            uint4 a = A4[(size_t)np * 16 + cc];
            uint4 b = B4[((size_t)n * 1024 + id) * 16 + cc];
            uint32_t aw[4] = {a.x, a.y, a.z, a.w};
            uint32_t bw[4] = {b.x, b.y, b.z, b.w};
#pragma unroll
            for (int j = 0; j < 4; j++) {
                float2 fa = __half22float2(*(__half2*)&aw[j]);
                float2 fb = __half22float2(*(__half2*)&bw[j]);
                float y0 = fa.x + fb.x, y1 = fa.y + fb.y;
                s[j * 2]     += y0; q[j * 2]     += y0 * y0;
                s[j * 2 + 1] += y1; q[j * 2 + 1] += y1 * y1;
            }
        }
#pragma unroll
        for (int j = 0; j < 8; j++) {
            atomicAdd(&ssum[c8 * 8 + j], s[j]);
            atomicAdd(&ssq [c8 * 8 + j], q[j]);
        }
        __syncthreads();
        if (threadIdx.x < 128) {
            atomicAdd(&d_sum  [threadIdx.x], ssum[threadIdx.x]);
            atomicAdd(&d_sumsq[threadIdx.x], ssq[threadIdx.x]);
        }
    } else {
        int b = blockIdx.x - 2048;            // 0..511 -> 64 rows each
        int c = threadIdx.x;                  // channel
        const float* base = d_SC + (size_t)b * 64 * 256 + c;
        float s = 0.f, q = 0.f;
#pragma unroll 8
        for (int r = 0; r < 64; r++) {
            float v = base[(size_t)r * 256];
            s += v; q += v * v;
        }
        atomicAdd(&d_sum  [3 * 256 + c], s);
        atomicAdd(&d_sumsq[3 * 256 + c], q);
    }
}

// ---------------------------------------------------------------------------
// fp16 mma GEMM with ldmatrix: BM=128, K=128 one-shot, 256 thr (8 warps 4x2),
// occ 2. N_TOT/128 column halves processed serially, A produced ONCE.
// Direct-store epilogue (round-9 layout; staged variant regressed).
// MODE 0: A = lrelu(BN0(gather Ah+Bh)), Y = y1 [ROWS,128]
// MODE 1: A = lrelu(BN1(y1)),           Y = y2 [ROWS,256]
// ---------------------------------------------------------------------------
#define KW 68
template <int N_TOT, int MODE>
__global__ void __launch_bounds__(256, 2) gemm_mma_kernel(
    const __half* __restrict__ Xin, const uint32_t* __restrict__ Wt,
    __half* __restrict__ Y, const float* __restrict__ g, const float* __restrict__ b) {
    constexpr int LAYER_IN  = MODE;
    constexpr int LAYER_OUT = MODE + 1;
    constexpr int NH = N_TOT / 128;
    extern __shared__ char smem_raw[];
    uint32_t* As = (uint32_t*)smem_raw;                    // [128][KW]
    uint32_t* Bs = As + 128 * KW;                          // [N_TOT][KW]
    float*  ssum = (float*)(Bs + N_TOT * KW);              // [N_TOT]
    float*  ssq  = ssum + N_TOT;                           // [N_TOT]
    float*  scs  = ssq + N_TOT;                            // [128]
    float*  shs  = scs + 128;                              // [128]

    const int tid = threadIdx.x;
    const int wid = tid >> 5;
    const int lane = tid & 31;
    const int gid = lane >> 2;
    const int tg  = lane & 3;
    const int warpRow = wid & 3;
    const int warpCol = wid >> 2;
    const int tileBase = blockIdx.x * 128;

    // inline finalize of BN(layer_in)
    if (tid < 128) {
        float mean = d_sum[LAYER_IN * 256 + tid] * (1.0f / (float)ROWS);
        float var  = d_sumsq[LAYER_IN * 256 + tid] * (1.0f / (float)ROWS) - mean * mean;
        float sc = g[tid] * rsqrtf(var + BN_EPS);
        scs[tid] = sc;
        shs[tid] = b[tid] - mean * sc;
    }
    for (int c2 = tid; c2 < N_TOT; c2 += 256) { ssum[c2] = 0.f; ssq[c2] = 0.f; }
    __syncthreads();

    // ---- B tile: packed copy from pre-transposed Wt ------------------------
    {
        const uint4* src = (const uint4*)Wt;
#pragma unroll
        for (int i = 0; i < N_TOT / 16; i++) {
            int e4 = tid + i * 256;
            int n = e4 >> 4, kw4 = e4 & 15;
            *(uint4*)&Bs[n * KW + kw4 * 4] = src[e4];
        }
    }

    // ---- A tile (fused gather/BN/lrelu producer, fp16 inputs) --------------
    int ids[8];
    if (MODE == 0) {
#pragma unroll
        for (int i = 0; i < 8; i++) {
            int r = (tid + i * 256) >> 4;
            ids[i] = __ldg(&d_idx[tileBase + r]);
        }
    }
#pragma unroll
    for (int i = 0; i < 8; i++) {
        int e = tid + i * 256;
        int r = e >> 4, cw = e & 15;
        int R = tileBase + r;
        float x[8];
        if (MODE == 0) {
            int np = R >> 4, n = R >> 14;
            uint4 ha = ((const uint4*)d_Ah)[(size_t)np * 16 + cw];
            uint4 hb = ((const uint4*)d_Bh)[((size_t)n * 1024 + ids[i]) * 16 + cw];
            uint32_t aw[4] = {ha.x, ha.y, ha.z, ha.w};
            uint32_t bw[4] = {hb.x, hb.y, hb.z, hb.w};
#pragma unroll
            for (int j = 0; j < 4; j++) {
                float2 fa = __half22float2(*(__half2*)&aw[j]);
                float2 fb = __half22float2(*(__half2*)&bw[j]);
                x[j * 2] = fa.x + fb.x; x[j * 2 + 1] = fa.y + fb.y;
            }
        } else {
            uint4 h = ((const uint4*)&Xin[(size_t)R * 128])[cw];
            uint32_t hw[4] = {h.x, h.y, h.z, h.w};
#pragma unroll
            for (int j = 0; j < 4; j++) {
                float2 f = __half22float2(*(__half2*)&hw[j]);
                x[j * 2] = f.x; x[j * 2 + 1] = f.y;
            }
        }
        const float* sc = &scs[cw * 8];
        const float* sh = &shs[cw * 8];
        float y[8];
#pragma unroll
        for (int j = 0; j < 8; j++) y[j] = lrelu(x[j] * sc[j] + sh[j]);
        uint4 v;
        v.x = pack_h2(y[0], y[1]); v.y = pack_h2(y[2], y[3]);
        v.z = pack_h2(y[4], y[5]); v.w = pack_h2(y[6], y[7]);
        *(uint4*)&As[r * KW + cw * 4] = v;
    }
    __syncthreads();

    // ---- ldmatrix base addresses (k-step 0), advance 32B per k-step --------
    const int t8 = lane >> 3, r8 = lane & 7;
    uint32_t aAddr[2], bAddr[4];
#pragma unroll
    for (int mi = 0; mi < 2; mi++) {
        int row = warpRow * 32 + mi * 16 + (t8 & 1) * 8 + r8;
        aAddr[mi] = smem_u32(&As[row * KW + (t8 >> 1) * 4]);
    }
#pragma unroll
    for (int nj = 0; nj < 4; nj++) {
        int row = warpCol * 64 + nj * 16 + (t8 >> 1) * 8 + r8;
        bAddr[nj] = smem_u32(&Bs[row * KW + (t8 & 1) * 4]);
    }

    // ---- loop over N halves: MMA + direct epilogue -------------------------
#pragma unroll
    for (int h = 0; h < NH; h++) {
        const uint32_t bOff = (uint32_t)h * 128u * KW * 4u;
        float c[2][8][4];
#pragma unroll
        for (int mi = 0; mi < 2; mi++)
#pragma unroll
            for (int ni = 0; ni < 8; ni++)
#pragma unroll
                for (int j = 0; j < 4; j++) c[mi][ni][j] = 0.f;

#pragma unroll
        for (int k0 = 0; k0 < 8; k0++) {
            uint32_t af[2][4], bf[4][4];
#pragma unroll
            for (int mi = 0; mi < 2; mi++) ldmatrix_x4(af[mi], aAddr[mi] + k0 * 32);
#pragma unroll
            for (int nj = 0; nj < 4; nj++) ldmatrix_x4(bf[nj], bAddr[nj] + bOff + k0 * 32);
#pragma unroll
            for (int mi = 0; mi < 2; mi++)
#pragma unroll
                for (int nj = 0; nj < 4; nj++) {
                    mma_f16(c[mi][nj * 2],     af[mi], &bf[nj][0]);
                    mma_f16(c[mi][nj * 2 + 1], af[mi], &bf[nj][2]);
                }
        }

        // store fp16 y + stats
#pragma unroll
        for (int mi = 0; mi < 2; mi++) {
            size_t r0 = (size_t)tileBase + warpRow * 32 + mi * 16 + gid;
#pragma unroll
            for (int ni = 0; ni < 8; ni++) {
                int col = h * 128 + warpCol * 64 + ni * 8 + tg * 2;
                __half2 v0 = __floats2half2_rn(c[mi][ni][0], c[mi][ni][1]);
                __half2 v1 = __floats2half2_rn(c[mi][ni][2], c[mi][ni][3]);
                *(__half2*)&Y[ r0      * N_TOT + col] = v0;
                *(__half2*)&Y[(r0 + 8) * N_TOT + col] = v1;
            }
        }
#pragma unroll
        for (int ni = 0; ni < 8; ni++) {
#pragma unroll
            for (int j = 0; j < 2; j++) {
                float s = c[0][ni][j] + c[0][ni][j + 2] + c[1][ni][j] + c[1][ni][j + 2];
                float q = c[0][ni][j]     * c[0][ni][j]
                        + c[0][ni][j + 2] * c[0][ni][j + 2]
                        + c[1][ni][j]     * c[1][ni][j]
                        + c[1][ni][j + 2] * c[1][ni][j + 2];
#pragma unroll
                for (int m = 16; m >= 4; m >>= 1) {
                    s += __shfl_xor_sync(0xffffffffu, s, m);
                    q += __shfl_xor_sync(0xffffffffu, q, m);
                }
                if (lane < 4) {
                    int cch = h * 128 + warpCol * 64 + ni * 8 + tg * 2 + j;
                    atomicAdd(&ssum[cch], s);
                    atomicAdd(&ssq [cch], q);
                }
            }
        }
    }
    __syncthreads();
    for (int c2 = tid; c2 < N_TOT; c2 += 256) {
        atomicAdd(&d_sum  [LAYER_OUT * 256 + c2], ssum[c2]);
        atomicAdd(&d_sumsq[LAYER_OUT * 256 + c2], ssq[c2]);
    }
}

// ---------------------------------------------------------------------------
// Final epilogue (vectorized): 1 thread = (np, 8-channel group).
// out = lrelu( BN_sc(SC) + mean_k lrelu(BN2(y2)) ); BN2/BN_sc finalize inline.
// uint4 (16B) y2 loads; warp reads 512B contiguous per k step.
// ---------------------------------------------------------------------------
__global__ void __launch_bounds__(256) final_kernel(
    float* __restrict__ out,
    const float* __restrict__ g2, const float* __restrict__ b2,
    const float* __restrict__ gsc, const float* __restrict__ bsc) {
    __shared__ float s2s[256], h2s[256], s3s[256], h3s[256];
    {
        int c = threadIdx.x;
        float mean2 = d_sum[2 * 256 + c] * (1.0f / (float)ROWS);
        float var2  = d_sumsq[2 * 256 + c] * (1.0f / (float)ROWS) - mean2 * mean2;
        float sc2 = g2[c] * rsqrtf(var2 + BN_EPS);
        s2s[c] = sc2; h2s[c] = b2[c] - mean2 * sc2;
        float mean3 = d_sum[3 * 256 + c] * (1.0f / (float)NPTS);
        float var3  = d_sumsq[3 * 256 + c] * (1.0f / (float)NPTS) - mean3 * mean3;
        float sc3 = gsc[c] * rsqrtf(var3 + BN_EPS);
        s3s[c] = sc3; h3s[c] = bsc[c] - mean3 * sc3;
    }
    __syncthreads();
    int t = blockIdx.x * blockDim.x + threadIdx.x;   // NPTS*32 threads
    int np = t >> 5, c8 = t & 31;                     // 8 channels per thread
    float s2[8], h2[8];
#pragma unroll
    for (int j = 0; j < 8; j++) { s2[j] = s2s[c8 * 8 + j]; h2[j] = h2s[c8 * 8 + j]; }

    const uint4* Y4 = (const uint4*)d_y2;             // 8 halves per uint4
    size_t base = (size_t)np * 512 + c8;              // row stride = 32 uint4
    float acc[8];
#pragma unroll
    for (int j = 0; j < 8; j++) acc[j] = 0.f;
#pragma unroll
    for (int k = 0; k < KNN; k++) {
        uint4 v = Y4[base + (size_t)k * 32];
        uint32_t wv[4] = {v.x, v.y, v.z, v.w};
#pragma unroll
        for (int j = 0; j < 4; j++) {
            float2 f = __half22float2(*(__half2*)&wv[j]);
            acc[j * 2]     += lrelu(f.x * s2[j * 2]     + h2[j * 2]);
            acc[j * 2 + 1] += lrelu(f.y * s2[j * 2 + 1] + h2[j * 2 + 1]);
        }
    }
    const float inv = 1.0f / (float)KNN;
    const float4* SC4 = (const float4*)d_SC;
    float4 sa = SC4[(size_t)np * 64 + c8 * 2];
    float4 sb = SC4[(size_t)np * 64 + c8 * 2 + 1];
    float scv[8] = {sa.x, sa.y, sa.z, sa.w, sb.x, sb.y, sb.z, sb.w};
    float o[8];
#pragma unroll
    for (int j = 0; j < 8; j++) {
        float r = scv[j] * s3s[c8 * 8 + j] + h3s[c8 * 8 + j] + acc[j] * inv;
        o[j] = lrelu(r);
    }
    float4* out4 = (float4*)out;
    out4[(size_t)np * 64 + c8 * 2]     = make_float4(o[0], o[1], o[2], o[3]);
    out4[(size_t)np * 64 + c8 * 2 + 1] = make_float4(o[4], o[5], o[6], o[7]);
}

// ---------------------------------------------------------------------------
// Launch (5 launches; mma2 at idx 3 -> ncu abs index 5 gets profiled)
// ---------------------------------------------------------------------------
extern "C" void kernel_launch(void* const* d_in, const int* in_sizes, int n_in,
                              void* d_out, int out_size) {
    const float* points   = (const float*)d_in[0];
    const float* features = (const float*)d_in[1];
    const float* W0  = (const float*)d_in[2];
    const float* g0  = (const float*)d_in[3];
    const float* b0  = (const float*)d_in[4];
    const float* W1  = (const float*)d_in[5];
    const float* g1  = (const float*)d_in[6];
    const float* b1  = (const float*)d_in[7];
    const float* W2  = (const float*)d_in[8];
    const float* g2  = (const float*)d_in[9];
    const float* b2  = (const float*)d_in[10];
    const float* Wsc = (const float*)d_in[11];
    const float* gsc = (const float*)d_in[12];
    const float* bsc = (const float*)d_in[13];
    float* out = (float*)d_out;

    __half *p1, *p2;
    uint32_t *pW1t, *pW2t;
    cudaGetSymbolAddress((void**)&p1,  d_y1);
    cudaGetSymbolAddress((void**)&p2,  d_y2);
    cudaGetSymbolAddress((void**)&pW1t, d_W1t);
    cudaGetSymbolAddress((void**)&pW2t, d_W2t);

    constexpr int SMEM_MMA1 = (128 * KW + 128 * KW) * 4 + (2 * 128 + 2 * 128) * 4;
    constexpr int SMEM_MMA2 = (128 * KW + 256 * KW) * 4 + (2 * 256 + 2 * 128) * 4;
    cudaFuncSetAttribute(gemm_mma_kernel<128, 0>,
                         cudaFuncAttributeMaxDynamicSharedMemorySize, SMEM_MMA1);
    cudaFuncSetAttribute(gemm_mma_kernel<256, 1>,
                         cudaFuncAttributeMaxDynamicSharedMemorySize, SMEM_MMA2);

    // 0: mega setup (knn + stats zero + W transposes + dual GEMM + SC GEMM)
    mega_kernel<<<1152, 256>>>(points, features, W0, Wsc, W1, W2);
    // 1: layer-0 virtual-y0 stats + SC stats
    stats_kernel<<<2560, 256>>>();
    // 2: layer-1 MMA (gather+BN0+lrelu fused; BN0 finalize inline)
    gemm_mma_kernel<128, 0><<<ROWS / 128, 256, SMEM_MMA1>>>(nullptr, pW1t, p1, g0, b0);
    // 3: layer-2 MMA (BN1+lrelu fused; both N-halves, A produced once) [PROFILED]
    gemm_mma_kernel<256, 1><<<ROWS / 128, 256, SMEM_MMA2>>>(p1, pW2t, p2, g1, b1);
    // 4: final epilogue (vectorized; BN2 + BN_sc finalize inline)
    final_kernel<<<NPTS * 32 / 256, 256>>>(out, g2, b2, gsc, bsc);
}

// round 14
// speedup vs baseline: 1.0635x; 1.0502x over previous
#include <cuda_runtime.h>
#include <cuda_fp16.h>
#include <math.h>
#include <cstdint>

#define NB   32
#define PP   1024
#define KNN  16
#define NPTS (NB * PP)       // 32768
#define ROWS (NPTS * KNN)    // 524288
#define LRELU_ALPHA 0.1f
#define BN_EPS 1e-3f
#define KW 68
#define KW4 (KW * 4)

// ---------------------------------------------------------------------------
// Static device scratch
// ---------------------------------------------------------------------------
__device__ __half d_Ah [NPTS * 128];
__device__ __half d_Bh [NPTS * 128];
__device__ float  d_SC [NPTS * 256];
__device__ __half d_y1 [ROWS * 128];
__device__ int    d_idx [ROWS];
__device__ uint32_t d_W1t[128 * 64];
__device__ uint32_t d_W2t[256 * 64];
__device__ float  d_sum  [4 * 256];
__device__ float  d_sumsq[4 * 256];
__device__ float  d_gram [128 * 128];
__device__ float  d_xsum [128];

__device__ __forceinline__ void mma_f16(float* d, const uint32_t* a, const uint32_t* b) {
    asm volatile(
        "mma.sync.aligned.m16n8k16.row.col.f32.f16.f16.f32 "
        "{%0,%1,%2,%3}, {%4,%5,%6,%7}, {%8,%9}, {%0,%1,%2,%3};"
        : "+f"(d[0]), "+f"(d[1]), "+f"(d[2]), "+f"(d[3])
        : "r"(a[0]), "r"(a[1]), "r"(a[2]), "r"(a[3]), "r"(b[0]), "r"(b[1]));
}
__device__ __forceinline__ void ldmatrix_x4(uint32_t* r, uint32_t addr) {
    asm volatile("ldmatrix.sync.aligned.m8n8.x4.shared.b16 {%0,%1,%2,%3}, [%4];"
                 : "=r"(r[0]), "=r"(r[1]), "=r"(r[2]), "=r"(r[3]) : "r"(addr));
}
__device__ __forceinline__ void ldmatrix_x4_trans(uint32_t* r, uint32_t addr) {
    asm volatile("ldmatrix.sync.aligned.m8n8.x4.trans.shared.b16 {%0,%1,%2,%3}, [%4];"
                 : "=r"(r[0]), "=r"(r[1]), "=r"(r[2]), "=r"(r[3]) : "r"(addr));
}
__device__ __forceinline__ uint32_t smem_u32(const void* p) {
    uint32_t a;
    asm("{ .reg .u64 t; cvta.to.shared.u64 t, %1; cvt.u32.u64 %0, t; }" : "=r"(a) : "l"(p));
    return a;
}
__device__ __forceinline__ uint32_t pack_h2(float lo, float hi) {
    __half2 h = __floats2half2_rn(lo, hi);
    return *(uint32_t*)&h;
}
__device__ __forceinline__ float lrelu(float x) {
    return x > 0.f ? x : LRELU_ALPHA * x;
}

// ---------------------------------------------------------------------------
// MEGA setup: [0,128) KNN (+zero stats/gram/xsum, W transposes);
// [128,640) dual GEMM A/B fp16; [640,1152) shortcut GEMM SC fp32.
// ---------------------------------------------------------------------------
__global__ void __launch_bounds__(256) mega_kernel(
    const float* __restrict__ pts, const float* __restrict__ feat,
    const float* __restrict__ W0,  const float* __restrict__ Wsc,
    const float* __restrict__ W1,  const float* __restrict__ W2) {
    __shared__ float sbuf[3072];
    const int bid = blockIdx.x;
    const int tid = threadIdx.x;

    if (bid < 128) {
        if (tid < 128) d_gram[bid * 128 + tid] = 0.f;
        else d_gram[bid * 128 + tid] = 0.f;   // tid 128..255 covers rest? no:
        // (cover full 128 floats with first 128 threads; second half redundant-safe)
        if (bid == 0) {
            for (int i = tid; i < 1024; i += 256) { d_sum[i] = 0.f; d_sumsq[i] = 0.f; }
            if (tid < 128) d_xsum[tid] = 0.f;
        } else if (bid == 1) {
            for (int t = tid; t < 128 * 64; t += 256) {
                int n = t >> 6, kw = t & 63;
                d_W1t[t] = pack_h2(W1[(size_t)(2 * kw) * 128 + n],
                                   W1[(size_t)(2 * kw + 1) * 128 + n]);
            }
        } else if (bid <= 3) {
            int base = (bid - 2) * 8192;
            for (int i = tid; i < 8192; i += 256) {
                int t = base + i;
                int n = t >> 6, kw = t & 63;
                d_W2t[t] = pack_h2(W2[(size_t)(2 * kw) * 256 + n],
                                   W2[(size_t)(2 * kw + 1) * 256 + n]);
            }
        }
        float* sx = sbuf;
        float* sy = sbuf + 1024;
        float* sz = sbuf + 2048;
        int n = bid >> 2;
        int p = ((bid & 3) << 8) + tid;
        const float* base = pts + (size_t)n * PP * 3;
        for (int i = tid; i < PP; i += 256) {
            sx[i] = base[i * 3 + 0];
            sy[i] = base[i * 3 + 1];
            sz[i] = base[i * 3 + 2];
        }
        __syncthreads();
        float qx = sx[p], qy = sy[p], qz = sz[p];
        float bd[KNN]; int bi[KNN];
#pragma unroll
        for (int i = 0; i < KNN; i++) { bd[i] = 3.0e38f; bi[i] = 0; }
        for (int q = 0; q < PP; q++) {
            float dx = sx[q] - qx, dy = sy[q] - qy, dz = sz[q] - qz;
            float d = dx * dx + dy * dy + dz * dz;
            if (q == p) continue;
            if (d < bd[KNN - 1]) {
                int j = KNN - 1;
                while (j > 0 && bd[j - 1] > d) { bd[j] = bd[j - 1]; bi[j] = bi[j - 1]; j--; }
                bd[j] = d; bi[j] = q;
            }
        }
        int ob = (n * PP + p) * KNN;
        for (int k = 0; k < KNN; k++) d_idx[ob + k] = bi[k];
        return;
    }

    const bool dual = bid < 640;
    const int sub = dual ? bid - 128 : bid - 640;
    const int rowBlock = sub & 255;
    const int ysel = sub >> 8;
    float* As = sbuf;
    float* Bs = sbuf + 1024;
    const int rowBase = rowBlock * 128;
    const int tx = tid & 15, ty = tid >> 4;
    float acc[8][8];
#pragma unroll
    for (int i = 0; i < 8; i++)
#pragma unroll
        for (int j = 0; j < 8; j++) acc[i][j] = 0.f;
    const int a_row = tid >> 1, a_k4 = (tid & 1) * 4;
    const int b_k = tid >> 5, b_n = (tid & 31) * 4;
#pragma unroll
    for (int k0 = 0; k0 < 64; k0 += 8) {
        float4 av = *(const float4*)&feat[(size_t)(rowBase + a_row) * 64 + k0 + a_k4];
        As[(a_k4 + 0) * 128 + a_row] = av.x;
        As[(a_k4 + 1) * 128 + a_row] = av.y;
        As[(a_k4 + 2) * 128 + a_row] = av.z;
        As[(a_k4 + 3) * 128 + a_row] = av.w;
        float4 bv;
        if (dual) {
            float4 bhi = *(const float4*)&W0[(size_t)(64 + k0 + b_k) * 128 + b_n];
            if (ysel == 0) {
                float4 blo = *(const float4*)&W0[(size_t)(k0 + b_k) * 128 + b_n];
                bv.x = blo.x - bhi.x; bv.y = blo.y - bhi.y;
                bv.z = blo.z - bhi.z; bv.w = blo.w - bhi.w;
            } else bv = bhi;
        } else {
            bv = *(const float4*)&Wsc[(size_t)(k0 + b_k) * 256 + ysel * 128 + b_n];
        }
        *(float4*)&Bs[b_k * 128 + b_n] = bv;
        __syncthreads();
#pragma unroll
        for (int kk = 0; kk < 8; kk++) {
            float4 a0 = *(const float4*)&As[kk * 128 + ty * 8];
            float4 a1 = *(const float4*)&As[kk * 128 + ty * 8 + 4];
            float4 b0 = *(const float4*)&Bs[kk * 128 + tx * 8];
            float4 b1 = *(const float4*)&Bs[kk * 128 + tx * 8 + 4];
            float a[8] = {a0.x, a0.y, a0.z, a0.w, a1.x, a1.y, a1.z, a1.w};
            float b[8] = {b0.x, b0.y, b0.z, b0.w, b1.x, b1.y, b1.z, b1.w};
#pragma unroll
            for (int i = 0; i < 8; i++)
#pragma unroll
                for (int j = 0; j < 8; j++) acc[i][j] += a[i] * b[j];
        }
        __syncthreads();
    }
    if (dual) {
        __half* Yh = ysel ? d_Bh : d_Ah;
#pragma unroll
        for (int i = 0; i < 8; i++) {
            int row = rowBase + ty * 8 + i;
            uint4 v;
            v.x = pack_h2(acc[i][0], acc[i][1]);
            v.y = pack_h2(acc[i][2], acc[i][3]);
            v.z = pack_h2(acc[i][4], acc[i][5]);
            v.w = pack_h2(acc[i][6], acc[i][7]);
            *(uint4*)&Yh[(size_t)row * 128 + tx * 8] = v;
        }
    } else {
#pragma unroll
        for (int i = 0; i < 8; i++) {
            int row = rowBase + ty * 8 + i;
            float4 c0 = {acc[i][0], acc[i][1], acc[i][2], acc[i][3]};
            float4 c1 = {acc[i][4], acc[i][5], acc[i][6], acc[i][7]};
            *(float4*)&d_SC[(size_t)row * 256 + ysel * 128 + tx * 8]     = c0;
            *(float4*)&d_SC[(size_t)row * 256 + ysel * 128 + tx * 8 + 4] = c1;
        }
    }
}

// ---------------------------------------------------------------------------
// Stats: [0,2048) layer-0 virtual-y0 stats; [2048,2560) SC stats (layer 3).
// ---------------------------------------------------------------------------
__global__ void __launch_bounds__(256) stats_kernel() {
    if (blockIdx.x < 2048) {
        const uint4* A4 = (const uint4*)d_Ah;
        const uint4* B4 = (const uint4*)d_Bh;
        __shared__ float ssum[128], ssq[128];
        if (threadIdx.x < 128) { ssum[threadIdx.x] = 0.f; ssq[threadIdx.x] = 0.f; }
        __syncthreads();
        const int start = blockIdx.x * 256 + threadIdx.x;
        const int c8 = start & 15;
        float s[8], q[8];
#pragma unroll
        for (int j = 0; j < 8; j++) { s[j] = 0.f; q[j] = 0.f; }
#pragma unroll 4
        for (int i = 0; i < 16; i++) {
            int e = start + i * 524288;
            int r = e >> 4, cc = e & 15;
            int np = r >> 4, n = r >> 14;
            int id = __ldg(&d_idx[r]);
            uint4 a = A4[(size_t)np * 16 + cc];
            uint4 b = B4[((size_t)n * 1024 + id) * 16 + cc];
            uint32_t aw[4] = {a.x, a.y, a.z, a.w};
            uint32_t bw[4] = {b.x, b.y, b.z, b.w};
#pragma unroll
            for (int j = 0; j < 4; j++) {
                float2 fa = __half22float2(*(__half2*)&aw[j]);
                float2 fb = __half22float2(*(__half2*)&bw[j]);
                float y0 = fa.x + fb.x, y1 = fa.y + fb.y;
                s[j * 2]     += y0; q[j * 2]     += y0 * y0;
                s[j * 2 + 1] += y1; q[j * 2 + 1] += y1 * y1;
            }
        }
#pragma unroll
        for (int j = 0; j < 8; j++) {
            atomicAdd(&ssum[c8 * 8 + j], s[j]);
            atomicAdd(&ssq [c8 * 8 + j], q[j]);
        }
        __syncthreads();
        if (threadIdx.x < 128) {
            atomicAdd(&d_sum  [threadIdx.x], ssum[threadIdx.x]);
            atomicAdd(&d_sumsq[threadIdx.x], ssq[threadIdx.x]);
        }
    } else {
        int b = blockIdx.x - 2048;
        int c = threadIdx.x;
        const float* base = d_SC + (size_t)b * 64 * 256 + c;
        float s = 0.f, q = 0.f;
#pragma unroll 8
        for (int r = 0; r < 64; r++) {
            float v = base[(size_t)r * 256];
            s += v; q += v * v;
        }
        atomicAdd(&d_sum  [3 * 256 + c], s);
        atomicAdd(&d_sumsq[3 * 256 + c], q);
    }
}

// ---------------------------------------------------------------------------
// Layer-1 MMA (unchanged path): gather+BN0+lrelu -> y1 fp16 + BN1 stats.
// ---------------------------------------------------------------------------
__global__ void __launch_bounds__(256, 2) gemm_mma1_kernel(
    const uint32_t* __restrict__ Wt, __half* __restrict__ Y,
    const float* __restrict__ g, const float* __restrict__ b) {
    extern __shared__ char smem_raw[];
    uint32_t* As = (uint32_t*)smem_raw;                    // [128][KW]
    uint32_t* Bs = As + 128 * KW;                          // [128][KW]
    float*  ssum = (float*)(Bs + 128 * KW);
    float*  ssq  = ssum + 128;
    float*  scs  = ssq + 128;
    float*  shs  = scs + 128;

    const int tid = threadIdx.x;
    const int wid = tid >> 5;
    const int lane = tid & 31;
    const int gid = lane >> 2;
    const int tg  = lane & 3;
    const int warpRow = wid & 3;
    const int warpCol = wid >> 2;
    const int tileBase = blockIdx.x * 128;

    if (tid < 128) {
        float mean = d_sum[tid] * (1.0f / (float)ROWS);
        float var  = d_sumsq[tid] * (1.0f / (float)ROWS) - mean * mean;
        float sc = g[tid] * rsqrtf(var + BN_EPS);
        scs[tid] = sc;
        shs[tid] = b[tid] - mean * sc;
        ssum[tid] = 0.f; ssq[tid] = 0.f;
    }
    __syncthreads();

    {
        const uint4* src = (const uint4*)Wt;
#pragma unroll
        for (int i = 0; i < 8; i++) {
            int e4 = tid + i * 256;
            int n = e4 >> 4, kw4 = e4 & 15;
            *(uint4*)&Bs[n * KW + kw4 * 4] = src[e4];
        }
    }
    int ids[8];
#pragma unroll
    for (int i = 0; i < 8; i++) {
        int r = (tid + i * 256) >> 4;
        ids[i] = __ldg(&d_idx[tileBase + r]);
    }
#pragma unroll
    for (int i = 0; i < 8; i++) {
        int e = tid + i * 256;
        int r = e >> 4, cw = e & 15;
        int R = tileBase + r;
        int np = R >> 4, n = R >> 14;
        uint4 ha = ((const uint4*)d_Ah)[(size_t)np * 16 + cw];
        uint4 hb = ((const uint4*)d_Bh)[((size_t)n * 1024 + ids[i]) * 16 + cw];
        uint32_t aw[4] = {ha.x, ha.y, ha.z, ha.w};
        uint32_t bw[4] = {hb.x, hb.y, hb.z, hb.w};
        float x[8];
#pragma unroll
        for (int j = 0; j < 4; j++) {
            float2 fa = __half22float2(*(__half2*)&aw[j]);
            float2 fb = __half22float2(*(__half2*)&bw[j]);
            x[j * 2] = fa.x + fb.x; x[j * 2 + 1] = fa.y + fb.y;
        }
        const float* sc = &scs[cw * 8];
        const float* sh = &shs[cw * 8];
        float y[8];
#pragma unroll
        for (int j = 0; j < 8; j++) y[j] = lrelu(x[j] * sc[j] + sh[j]);
        uint4 v;
        v.x = pack_h2(y[0], y[1]); v.y = pack_h2(y[2], y[3]);
        v.z = pack_h2(y[4], y[5]); v.w = pack_h2(y[6], y[7]);
        *(uint4*)&As[r * KW + cw * 4] = v;
    }
    __syncthreads();

    const int t8 = lane >> 3, r8 = lane & 7;
    uint32_t aAddr[2], bAddr[4];
#pragma unroll
    for (int mi = 0; mi < 2; mi++) {
        int row = warpRow * 32 + mi * 16 + (t8 & 1) * 8 + r8;
        aAddr[mi] = smem_u32(&As[row * KW + (t8 >> 1) * 4]);
    }
#pragma unroll
    for (int nj = 0; nj < 4; nj++) {
        int row = warpCol * 64 + nj * 16 + (t8 >> 1) * 8 + r8;
        bAddr[nj] = smem_u32(&Bs[row * KW + (t8 & 1) * 4]);
    }

    float c[2][8][4];
#pragma unroll
    for (int mi = 0; mi < 2; mi++)
#pragma unroll
        for (int ni = 0; ni < 8; ni++)
#pragma unroll
            for (int j = 0; j < 4; j++) c[mi][ni][j] = 0.f;
#pragma unroll
    for (int k0 = 0; k0 < 8; k0++) {
        uint32_t af[2][4], bf[4][4];
#pragma unroll
        for (int mi = 0; mi < 2; mi++) ldmatrix_x4(af[mi], aAddr[mi] + k0 * 32);
#pragma unroll
        for (int nj = 0; nj < 4; nj++) ldmatrix_x4(bf[nj], bAddr[nj] + k0 * 32);
#pragma unroll
        for (int mi = 0; mi < 2; mi++)
#pragma unroll
            for (int nj = 0; nj < 4; nj++) {
                mma_f16(c[mi][nj * 2],     af[mi], &bf[nj][0]);
                mma_f16(c[mi][nj * 2 + 1], af[mi], &bf[nj][2]);
            }
    }
#pragma unroll
    for (int mi = 0; mi < 2; mi++) {
        size_t r0 = (size_t)tileBase + warpRow * 32 + mi * 16 + gid;
#pragma unroll
        for (int ni = 0; ni < 8; ni++) {
            int col = warpCol * 64 + ni * 8 + tg * 2;
            __half2 v0 = __floats2half2_rn(c[mi][ni][0], c[mi][ni][1]);
            __half2 v1 = __floats2half2_rn(c[mi][ni][2], c[mi][ni][3]);
            *(__half2*)&Y[ r0      * 128 + col] = v0;
            *(__half2*)&Y[(r0 + 8) * 128 + col] = v1;
        }
    }
#pragma unroll
    for (int ni = 0; ni < 8; ni++) {
#pragma unroll
        for (int j = 0; j < 2; j++) {
            float s = c[0][ni][j] + c[0][ni][j + 2] + c[1][ni][j] + c[1][ni][j + 2];
            float q = c[0][ni][j]     * c[0][ni][j]
                    + c[0][ni][j + 2] * c[0][ni][j + 2]
                    + c[1][ni][j]     * c[1][ni][j]
                    + c[1][ni][j + 2] * c[1][ni][j + 2];
#pragma unroll
            for (int m = 16; m >= 4; m >>= 1) {
                s += __shfl_xor_sync(0xffffffffu, s, m);
                q += __shfl_xor_sync(0xffffffffu, q, m);
            }
            if (lane < 4) {
                int cch = warpCol * 64 + ni * 8 + tg * 2 + j;
                atomicAdd(&ssum[cch], s);
                atomicAdd(&ssq [cch], q);
            }
        }
    }
    __syncthreads();
    if (tid < 128) {
        atomicAdd(&d_sum  [256 + tid], ssum[tid]);
        atomicAdd(&d_sumsq[256 + tid], ssq[tid]);
    }
}

// ---------------------------------------------------------------------------
// Gram kernel: G = X2^T X2 and xsum = sum_rows X2, X2 = fp16(lrelu(BN1(y1))).
// 256 CTAs x 2048 rows (16 tiles of 128). Tensor-core syrk via ldmatrix.trans.
// ---------------------------------------------------------------------------
__global__ void __launch_bounds__(256, 2) gram_kernel(
    const float* __restrict__ g, const float* __restrict__ b) {
    __shared__ uint32_t As[128 * KW];
    __shared__ float scs[128], shs[128], ssum[128];

    const int tid = threadIdx.x;
    const int wid = tid >> 5;
    const int lane = tid & 31;
    const int gid = lane >> 2;
    const int tg  = lane & 3;
    const int warpRow = wid & 3;
    const int warpCol = wid >> 2;
    const int t8 = lane >> 3, r8 = lane & 7;
    const int cw = tid & 15;

    if (tid < 128) {
        float mean = d_sum[256 + tid] * (1.0f / (float)ROWS);
        float var  = d_sumsq[256 + tid] * (1.0f / (float)ROWS) - mean * mean;
        float sc = g[tid] * rsqrtf(var + BN_EPS);
        scs[tid] = sc;
        shs[tid] = b[tid] - mean * sc;
        ssum[tid] = 0.f;
    }
    __syncthreads();

    // trans fragment base addresses (k-row part + channel halfword column)
    uint32_t base = smem_u32(As);
    uint32_t aT[2], bT[4];
#pragma unroll
    for (int mi = 0; mi < 2; mi++) {
        int mbase = warpRow * 32 + mi * 16 + (t8 & 1) * 8;
        aT[mi] = base + (uint32_t)(((t8 >> 1) * 8 + r8) * KW4) + (uint32_t)(mbase * 2);
    }
#pragma unroll
    for (int nj = 0; nj < 4; nj++) {
        int nbase = warpCol * 64 + nj * 16 + (t8 >> 1) * 8;
        bT[nj] = base + (uint32_t)(((t8 & 1) * 8 + r8) * KW4) + (uint32_t)(nbase * 2);
    }

    float c[2][8][4];
#pragma unroll
    for (int mi = 0; mi < 2; mi++)
#pragma unroll
        for (int ni = 0; ni < 8; ni++)
#pragma unroll
            for (int j = 0; j < 4; j++) c[mi][ni][j] = 0.f;
    float xs[8];
#pragma unroll
    for (int j = 0; j < 8; j++) xs[j] = 0.f;

    for (int t = 0; t < 16; t++) {
        int rowBase = blockIdx.x * 2048 + t * 128;
#pragma unroll
        for (int i = 0; i < 8; i++) {
            int e = tid + i * 256;
            int r = e >> 4;
            uint4 h = ((const uint4*)&d_y1[(size_t)(rowBase + r) * 128])[cw];
            uint32_t hw[4] = {h.x, h.y, h.z, h.w};
            const float* sc = &scs[cw * 8];
            const float* sh = &shs[cw * 8];
            float y[8];
#pragma unroll
            for (int j = 0; j < 4; j++) {
                float2 f = __half22float2(*(__half2*)&hw[j]);
                y[j * 2]     = lrelu(f.x * sc[j * 2]     + sh[j * 2]);
                y[j * 2 + 1] = lrelu(f.y * sc[j * 2 + 1] + sh[j * 2 + 1]);
            }
            uint4 v;
            v.x = pack_h2(y[0], y[1]); v.y = pack_h2(y[2], y[3]);
            v.z = pack_h2(y[4], y[5]); v.w = pack_h2(y[6], y[7]);
            // accumulate xsum from the ROUNDED values (consistency with MMA)
            uint32_t vv[4] = {v.x, v.y, v.z, v.w};
#pragma unroll
            for (int j = 0; j < 4; j++) {
                float2 f = __half22float2(*(__half2*)&vv[j]);
                xs[j * 2] += f.x; xs[j * 2 + 1] += f.y;
            }
            *(uint4*)&As[r * KW + cw * 4] = v;
        }
        __syncthreads();
#pragma unroll
        for (int k0 = 0; k0 < 8; k0++) {
            uint32_t off = (uint32_t)(k0 * 16 * KW4);
            uint32_t af[2][4], bf[4][4];
#pragma unroll
            for (int mi = 0; mi < 2; mi++) ldmatrix_x4_trans(af[mi], aT[mi] + off);
#pragma unroll
            for (int nj = 0; nj < 4; nj++) ldmatrix_x4_trans(bf[nj], bT[nj] + off);
#pragma unroll
            for (int mi = 0; mi < 2; mi++)
#pragma unroll
                for (int nj = 0; nj < 4; nj++) {
                    mma_f16(c[mi][nj * 2],     af[mi], &bf[nj][0]);
                    mma_f16(c[mi][nj * 2 + 1], af[mi], &bf[nj][2]);
                }
        }
        __syncthreads();
    }

    // accumulate G
#pragma unroll
    for (int mi = 0; mi < 2; mi++) {
        int m0 = warpRow * 32 + mi * 16 + gid;
#pragma unroll
        for (int ni = 0; ni < 8; ni++) {
            int n0 = warpCol * 64 + ni * 8 + tg * 2;
            atomicAdd(&d_gram[ m0      * 128 + n0    ], c[mi][ni][0]);
            atomicAdd(&d_gram[ m0      * 128 + n0 + 1], c[mi][ni][1]);
            atomicAdd(&d_gram[(m0 + 8) * 128 + n0    ], c[mi][ni][2]);
            atomicAdd(&d_gram[(m0 + 8) * 128 + n0 + 1], c[mi][ni][3]);
        }
    }
#pragma unroll
    for (int j = 0; j < 8; j++) atomicAdd(&ssum[cw * 8 + j], xs[j]);
    __syncthreads();
    if (tid < 128) atomicAdd(&d_xsum[tid], ssum[tid]);
}

// ---------------------------------------------------------------------------
// BN2 prep: per channel c, sum = xsum.w_c ; sumsq = w_c^T G w_c.
// grid 256 x 128 thr.
// ---------------------------------------------------------------------------
__global__ void __launch_bounds__(128) bn2_prep_kernel() {
    const int c = blockIdx.x;
    const int tid = threadIdx.x;
    __shared__ float w[128];
    __shared__ float red[8];
    if (tid < 64) {
        uint32_t p = d_W2t[c * 64 + tid];
        float2 f = __half22float2(*(__half2*)&p);
        w[2 * tid] = f.x; w[2 * tid + 1] = f.y;
    }
    __syncthreads();
    float wj = w[tid];
    float v = 0.f;
#pragma unroll 8
    for (int i = 0; i < 128; i++) v += w[i] * d_gram[i * 128 + tid];
    float q = wj * v;
    float s = wj * d_xsum[tid];
#pragma unroll
    for (int m = 16; m >= 1; m >>= 1) {
        q += __shfl_xor_sync(0xffffffffu, q, m);
        s += __shfl_xor_sync(0xffffffffu, s, m);
    }
    if ((tid & 31) == 0) { red[(tid >> 5) * 2] = q; red[(tid >> 5) * 2 + 1] = s; }
    __syncthreads();
    if (tid == 0) {
        d_sumsq[512 + c] = red[0] + red[2] + red[4] + red[6];
        d_sum  [512 + c] = red[1] + red[3] + red[5] + red[7];
    }
}

// ---------------------------------------------------------------------------
// Layer-2 MMA + fused k-mean + shortcut + final lrelu -> out (y2 never stored).
// 256 thr, occ 2; two N-halves with B reload; BN1/BN2/BN3 finalize inline.
// ---------------------------------------------------------------------------
__global__ void __launch_bounds__(256, 2) mma2_out_kernel(
    const float* __restrict__ g1, const float* __restrict__ b1,
    const float* __restrict__ g2, const float* __restrict__ b2,
    const float* __restrict__ gsc, const float* __restrict__ bsc,
    float* __restrict__ out) {
    extern __shared__ char smem_raw[];
    uint32_t* As = (uint32_t*)smem_raw;                    // [128][KW]
    uint32_t* Bs = As + 128 * KW;                          // [128][KW]
    float* fts = (float*)(Bs + 128 * KW);                  // [8][256]
    float* scs = fts + 8 * 256;                            // [128]
    float* shs = scs + 128;                                // [128]
    float* s2s = shs + 128;                                // [256]
    float* h2s = s2s + 256;                                // [256]
    float* s3s = h2s + 256;                                // [256]
    float* h3s = s3s + 256;                                // [256]

    const int tid = threadIdx.x;
    const int wid = tid >> 5;
    const int lane = tid & 31;
    const int tg  = lane & 3;
    const int warpRow = wid & 3;
    const int warpCol = wid >> 2;
    const int tileBase = blockIdx.x * 128;

    if (tid < 128) {
        float mean = d_sum[256 + tid] * (1.0f / (float)ROWS);
        float var  = d_sumsq[256 + tid] * (1.0f / (float)ROWS) - mean * mean;
        float sc = g1[tid] * rsqrtf(var + BN_EPS);
        scs[tid] = sc;
        shs[tid] = b1[tid] - mean * sc;
    }
    {
        int cch = tid;   // 0..255
        float mean2 = d_sum[512 + cch] * (1.0f / (float)ROWS);
        float var2  = d_sumsq[512 + cch] * (1.0f / (float)ROWS) - mean2 * mean2;
        float sc2 = g2[cch] * rsqrtf(var2 + BN_EPS);
        s2s[cch] = sc2; h2s[cch] = b2[cch] - mean2 * sc2;
        float mean3 = d_sum[768 + cch] * (1.0f / (float)NPTS);
        float var3  = d_sumsq[768 + cch] * (1.0f / (float)NPTS) - mean3 * mean3;
        float sc3 = gsc[cch] * rsqrtf(var3 + BN_EPS);
        s3s[cch] = sc3; h3s[cch] = bsc[cch] - mean3 * sc3;
    }
    __syncthreads();

    // A tile (x2 = lrelu(BN1(y1))) + B half 0
#pragma unroll
    for (int i = 0; i < 8; i++) {
        int e = tid + i * 256;
        int r = e >> 4, cw = e & 15;
        uint4 h = ((const uint4*)&d_y1[(size_t)(tileBase + r) * 128])[cw];
        uint32_t hw[4] = {h.x, h.y, h.z, h.w};
        const float* sc = &scs[cw * 8];
        const float* sh = &shs[cw * 8];
        float y[8];
#pragma unroll
        for (int j = 0; j < 4; j++) {
            float2 f = __half22float2(*(__half2*)&hw[j]);
            y[j * 2]     = lrelu(f.x * sc[j * 2]     + sh[j * 2]);
            y[j * 2 + 1] = lrelu(f.y * sc[j * 2 + 1] + sh[j * 2 + 1]);
        }
        uint4 v;
        v.x = pack_h2(y[0], y[1]); v.y = pack_h2(y[2], y[3]);
        v.z = pack_h2(y[4], y[5]); v.w = pack_h2(y[6], y[7]);
        *(uint4*)&As[r * KW + cw * 4] = v;
    }
    {
        const uint4* src = (const uint4*)d_W2t;
#pragma unroll
        for (int i = 0; i < 8; i++) {
            int e4 = tid + i * 256;
            int n = e4 >> 4, kw4 = e4 & 15;
            *(uint4*)&Bs[n * KW + kw4 * 4] = src[e4];
        }
    }
    __syncthreads();

    const int t8 = lane >> 3, r8 = lane & 7;
    uint32_t aAddr[2], bAddr[4];
#pragma unroll
    for (int mi = 0; mi < 2; mi++) {
        int row = warpRow * 32 + mi * 16 + (t8 & 1) * 8 + r8;
        aAddr[mi] = smem_u32(&As[row * KW + (t8 >> 1) * 4]);
    }
#pragma unroll
    for (int nj = 0; nj < 4; nj++) {
        int row = warpCol * 64 + nj * 16 + (t8 >> 1) * 8 + r8;
        bAddr[nj] = smem_u32(&Bs[row * KW + (t8 & 1) * 4]);
    }

#pragma unroll
    for (int h = 0; h < 2; h++) {
        if (h == 1) {
            __syncthreads();    // all warps done reading Bs half 0
            const uint4* src = (const uint4*)d_W2t + 2048;
#pragma unroll
            for (int i = 0; i < 8; i++) {
                int e4 = tid + i * 256;
                int n = e4 >> 4, kw4 = e4 & 15;
                *(uint4*)&Bs[n * KW + kw4 * 4] = src[e4];
            }
            __syncthreads();
        }
        float c[2][8][4];
#pragma unroll
        for (int mi = 0; mi < 2; mi++)
#pragma unroll
            for (int ni = 0; ni < 8; ni++)
#pragma unroll
                for (int j = 0; j < 4; j++) c[mi][ni][j] = 0.f;
#pragma unroll
        for (int k0 = 0; k0 < 8; k0++) {
            uint32_t af[2][4], bf[4][4];
#pragma unroll
            for (int mi = 0; mi < 2; mi++) ldmatrix_x4(af[mi], aAddr[mi] + k0 * 32);
#pragma unroll
            for (int nj = 0; nj < 4; nj++) ldmatrix_x4(bf[nj], bAddr[nj] + k0 * 32);
#pragma unroll
            for (int mi = 0; mi < 2; mi++)
#pragma unroll
                for (int nj = 0; nj < 4; nj++) {
                    mma_f16(c[mi][nj * 2],     af[mi], &bf[nj][0]);
                    mma_f16(c[mi][nj * 2 + 1], af[mi], &bf[nj][2]);
                }
        }
        // k-mean epilogue: BN2 + lrelu + reduce 16 rows per np group
#pragma unroll
        for (int mi = 0; mi < 2; mi++) {
            int npL = warpRow * 2 + mi;
#pragma unroll
            for (int ni = 0; ni < 8; ni++) {
#pragma unroll
                for (int j = 0; j < 2; j++) {
                    int cch = h * 128 + warpCol * 64 + ni * 8 + tg * 2 + j;
                    float sv = s2s[cch], hv = h2s[cch];
                    float p = lrelu(c[mi][ni][j] * sv + hv)
                            + lrelu(c[mi][ni][j + 2] * sv + hv);
#pragma unroll
                    for (int m = 16; m >= 4; m >>= 1)
                        p += __shfl_xor_sync(0xffffffffu, p, m);
                    if (lane < 4) fts[npL * 256 + cch] = p;
                }
            }
        }
    }
    __syncthreads();

    // out = lrelu( BN_sc(SC) + fts/16 )
    const int npBase = blockIdx.x * 8;
#pragma unroll
    for (int i = 0; i < 2; i++) {
        int e4 = tid + i * 256;
        int npL = e4 >> 6, c4 = e4 & 63;
        float4 sc = ((const float4*)d_SC)[(size_t)(npBase + npL) * 64 + c4];
        float4 f  = ((const float4*)fts)[npL * 64 + c4];
        const float inv = 1.0f / 16.0f;
        float4 o;
        o.x = lrelu(sc.x * s3s[c4 * 4 + 0] + h3s[c4 * 4 + 0] + f.x * inv);
        o.y = lrelu(sc.y * s3s[c4 * 4 + 1] + h3s[c4 * 4 + 1] + f.y * inv);
        o.z = lrelu(sc.z * s3s[c4 * 4 + 2] + h3s[c4 * 4 + 2] + f.z * inv);
        o.w = lrelu(sc.w * s3s[c4 * 4 + 3] + h3s[c4 * 4 + 3] + f.w * inv);
        ((float4*)out)[(size_t)(npBase + npL) * 64 + c4] = o;
    }
}

// ---------------------------------------------------------------------------
// Launch (6 launches; gram at idx 3 -> ncu abs index 5)
// ---------------------------------------------------------------------------
extern "C" void kernel_launch(void* const* d_in, const int* in_sizes, int n_in,
                              void* d_out, int out_size) {
    const float* points   = (const float*)d_in[0];
    const float* features = (const float*)d_in[1];
    const float* W0  = (const float*)d_in[2];
    const float* g0  = (const float*)d_in[3];
    const float* b0  = (const float*)d_in[4];
    const float* W1  = (const float*)d_in[5];
    const float* g1  = (const float*)d_in[6];
    const float* b1  = (const float*)d_in[7];
    const float* W2  = (const float*)d_in[8];
    const float* g2  = (const float*)d_in[9];
    const float* b2  = (const float*)d_in[10];
    const float* Wsc = (const float*)d_in[11];
    const float* gsc = (const float*)d_in[12];
    const float* bsc = (const float*)d_in[13];
    float* out = (float*)d_out;

    __half* p1;
    uint32_t* pW1t;
    cudaGetSymbolAddress((void**)&p1,  d_y1);
    cudaGetSymbolAddress((void**)&pW1t, d_W1t);

    constexpr int SMEM_MMA1 = (2 * 128 * KW) * 4 + 4 * 128 * 4;
    constexpr int SMEM_OUT  = (2 * 128 * KW) * 4 + 8 * 256 * 4 + (2 * 128 + 4 * 256) * 4;
    cudaFuncSetAttribute(gemm_mma1_kernel,
                         cudaFuncAttributeMaxDynamicSharedMemorySize, SMEM_MMA1);
    cudaFuncSetAttribute(mma2_out_kernel,
                         cudaFuncAttributeMaxDynamicSharedMemorySize, SMEM_OUT);

    // 0: mega setup
    mega_kernel<<<1152, 256>>>(points, features, W0, Wsc, W1, W2);
    // 1: layer-0 virtual-y0 stats + SC stats
    stats_kernel<<<2560, 256>>>();
    // 2: layer-1 MMA -> y1 + BN1 stats
    gemm_mma1_kernel<<<ROWS / 128, 256, SMEM_MMA1>>>(pW1t, p1, g0, b0);
    // 3: Gram of x2 + xsum (tensor syrk)  [PROFILED]
    gram_kernel<<<256, 256>>>(g1, b1);
    // 4: BN2 stats from Gram
    bn2_prep_kernel<<<256, 128>>>();
    // 5: layer-2 MMA + k-mean + shortcut + out
    mma2_out_kernel<<<ROWS / 128, 256, SMEM_OUT>>>(g1, b1, g2, b2, gsc, bsc, out);
}

// round 16
// speedup vs baseline: 1.2592x; 1.1839x over previous
#include <cuda_runtime.h>
#include <cuda_fp16.h>
#include <math.h>
#include <cstdint>

#define NB   32
#define PP   1024
#define KNN  16
#define NPTS (NB * PP)       // 32768
#define ROWS (NPTS * KNN)    // 524288
#define LRELU_ALPHA 0.1f
#define BN_EPS 1e-3f
#define KW 68
#define KW4 (KW * 4)

// ---------------------------------------------------------------------------
// Static device scratch
// ---------------------------------------------------------------------------
__device__ __half d_Ah [NPTS * 128];
__device__ __half d_Bh [NPTS * 128];
__device__ float  d_SC [NPTS * 256];
__device__ __half d_y1 [ROWS * 128];
__device__ int    d_idx [ROWS];
__device__ uint32_t d_W1t[128 * 64];
__device__ uint32_t d_W2t[256 * 64];
__device__ float  d_sum  [4 * 256];
__device__ float  d_sumsq[4 * 256];
__device__ float  d_gram [128 * 128];
__device__ float  d_xsum [128];

__device__ __forceinline__ void mma_f16(float* d, const uint32_t* a, const uint32_t* b) {
    asm volatile(
        "mma.sync.aligned.m16n8k16.row.col.f32.f16.f16.f32 "
        "{%0,%1,%2,%3}, {%4,%5,%6,%7}, {%8,%9}, {%0,%1,%2,%3};"
        : "+f"(d[0]), "+f"(d[1]), "+f"(d[2]), "+f"(d[3])
        : "r"(a[0]), "r"(a[1]), "r"(a[2]), "r"(a[3]), "r"(b[0]), "r"(b[1]));
}
__device__ __forceinline__ void ldmatrix_x4(uint32_t* r, uint32_t addr) {
    asm volatile("ldmatrix.sync.aligned.m8n8.x4.shared.b16 {%0,%1,%2,%3}, [%4];"
                 : "=r"(r[0]), "=r"(r[1]), "=r"(r[2]), "=r"(r[3]) : "r"(addr));
}
__device__ __forceinline__ void ldmatrix_x4_trans(uint32_t* r, uint32_t addr) {
    asm volatile("ldmatrix.sync.aligned.m8n8.x4.trans.shared.b16 {%0,%1,%2,%3}, [%4];"
                 : "=r"(r[0]), "=r"(r[1]), "=r"(r[2]), "=r"(r[3]) : "r"(addr));
}
__device__ __forceinline__ uint32_t smem_u32(const void* p) {
    uint32_t a;
    asm("{ .reg .u64 t; cvta.to.shared.u64 t, %1; cvt.u32.u64 %0, t; }" : "=r"(a) : "l"(p));
    return a;
}
__device__ __forceinline__ uint32_t pack_h2(float lo, float hi) {
    __half2 h = __floats2half2_rn(lo, hi);
    return *(uint32_t*)&h;
}
__device__ __forceinline__ float lrelu(float x) {
    return x > 0.f ? x : LRELU_ALPHA * x;
}

// ---------------------------------------------------------------------------
// MEGA setup: [0,128) KNN (register-resident top-16) + side duties;
// [128,640) dual GEMM A/B fp16; [640,1152) shortcut GEMM SC fp32.
// ---------------------------------------------------------------------------
__global__ void __launch_bounds__(256) mega_kernel(
    const float* __restrict__ pts, const float* __restrict__ feat,
    const float* __restrict__ W0,  const float* __restrict__ Wsc,
    const float* __restrict__ W1,  const float* __restrict__ W2) {
    __shared__ float sbuf[3072];
    const int bid = blockIdx.x;
    const int tid = threadIdx.x;

    if (bid < 128) {
        // ---- side duties -------------------------------------------------
        if (bid < 64) d_gram[bid * 256 + tid] = 0.f;     // 64*256 = 16384
        if (bid == 64) {
            for (int i = tid; i < 1024; i += 256) { d_sum[i] = 0.f; d_sumsq[i] = 0.f; }
            if (tid < 128) d_xsum[tid] = 0.f;
        } else if (bid == 65) {
            for (int t = tid; t < 128 * 64; t += 256) {
                int n = t >> 6, kw = t & 63;
                d_W1t[t] = pack_h2(W1[(size_t)(2 * kw) * 128 + n],
                                   W1[(size_t)(2 * kw + 1) * 128 + n]);
            }
        } else if (bid == 66 || bid == 67) {
            int base = (bid - 66) * 8192;
            for (int i = tid; i < 8192; i += 256) {
                int t = base + i;
                int n = t >> 6, kw = t & 63;
                d_W2t[t] = pack_h2(W2[(size_t)(2 * kw) * 256 + n],
                                   W2[(size_t)(2 * kw + 1) * 256 + n]);
            }
        }
        // ---- knn (register-resident) --------------------------------------
        float* sx = sbuf;
        float* sy = sbuf + 1024;
        float* sz = sbuf + 2048;
        int n = bid >> 2;
        int p = ((bid & 3) << 8) + tid;
        const float* base = pts + (size_t)n * PP * 3;
        for (int i = tid; i < PP; i += 256) {
            sx[i] = base[i * 3 + 0];
            sy[i] = base[i * 3 + 1];
            sz[i] = base[i * 3 + 2];
        }
        __syncthreads();
        float qx = sx[p], qy = sy[p], qz = sz[p];
        float bd[KNN]; int bi[KNN];
#pragma unroll
        for (int i = 0; i < KNN; i++) { bd[i] = 3.0e38f; bi[i] = 0; }
        for (int q = 0; q < PP; q++) {
            float dx = sx[q] - qx, dy = sy[q] - qy, dz = sz[q] - qz;
            float d = dx * dx + dy * dy + dz * dz;
            if (q == p) continue;
            if (d < bd[KNN - 1]) {
                // bubble-insert with STATIC indices -> stays in registers
                float cd = d; int ci = q;
#pragma unroll
                for (int j = 0; j < KNN; j++) {
                    if (cd < bd[j]) {
                        float td = bd[j]; int ti = bi[j];
                        bd[j] = cd; bi[j] = ci;
                        cd = td; ci = ti;
                    }
                }
            }
        }
        int ob = (n * PP + p) * KNN;
#pragma unroll
        for (int k = 0; k < KNN; k++) d_idx[ob + k] = bi[k];
        return;
    }

    const bool dual = bid < 640;
    const int sub = dual ? bid - 128 : bid - 640;
    const int rowBlock = sub & 255;
    const int ysel = sub >> 8;
    float* As = sbuf;
    float* Bs = sbuf + 1024;
    const int rowBase = rowBlock * 128;
    const int tx = tid & 15, ty = tid >> 4;
    float acc[8][8];
#pragma unroll
    for (int i = 0; i < 8; i++)
#pragma unroll
        for (int j = 0; j < 8; j++) acc[i][j] = 0.f;
    const int a_row = tid >> 1, a_k4 = (tid & 1) * 4;
    const int b_k = tid >> 5, b_n = (tid & 31) * 4;
#pragma unroll
    for (int k0 = 0; k0 < 64; k0 += 8) {
        float4 av = *(const float4*)&feat[(size_t)(rowBase + a_row) * 64 + k0 + a_k4];
        As[(a_k4 + 0) * 128 + a_row] = av.x;
        As[(a_k4 + 1) * 128 + a_row] = av.y;
        As[(a_k4 + 2) * 128 + a_row] = av.z;
        As[(a_k4 + 3) * 128 + a_row] = av.w;
        float4 bv;
        if (dual) {
            float4 bhi = *(const float4*)&W0[(size_t)(64 + k0 + b_k) * 128 + b_n];
            if (ysel == 0) {
                float4 blo = *(const float4*)&W0[(size_t)(k0 + b_k) * 128 + b_n];
                bv.x = blo.x - bhi.x; bv.y = blo.y - bhi.y;
                bv.z = blo.z - bhi.z; bv.w = blo.w - bhi.w;
            } else bv = bhi;
        } else {
            bv = *(const float4*)&Wsc[(size_t)(k0 + b_k) * 256 + ysel * 128 + b_n];
        }
        *(float4*)&Bs[b_k * 128 + b_n] = bv;
        __syncthreads();
#pragma unroll
        for (int kk = 0; kk < 8; kk++) {
            float4 a0 = *(const float4*)&As[kk * 128 + ty * 8];
            float4 a1 = *(const float4*)&As[kk * 128 + ty * 8 + 4];
            float4 b0 = *(const float4*)&Bs[kk * 128 + tx * 8];
            float4 b1 = *(const float4*)&Bs[kk * 128 + tx * 8 + 4];
            float a[8] = {a0.x, a0.y, a0.z, a0.w, a1.x, a1.y, a1.z, a1.w};
            float b[8] = {b0.x, b0.y, b0.z, b0.w, b1.x, b1.y, b1.z, b1.w};
#pragma unroll
            for (int i = 0; i < 8; i++)
#pragma unroll
                for (int j = 0; j < 8; j++) acc[i][j] += a[i] * b[j];
        }
        __syncthreads();
    }
    if (dual) {
        __half* Yh = ysel ? d_Bh : d_Ah;
#pragma unroll
        for (int i = 0; i < 8; i++) {
            int row = rowBase + ty * 8 + i;
            uint4 v;
            v.x = pack_h2(acc[i][0], acc[i][1]);
            v.y = pack_h2(acc[i][2], acc[i][3]);
            v.z = pack_h2(acc[i][4], acc[i][5]);
            v.w = pack_h2(acc[i][6], acc[i][7]);
            *(uint4*)&Yh[(size_t)row * 128 + tx * 8] = v;
        }
    } else {
#pragma unroll
        for (int i = 0; i < 8; i++) {
            int row = rowBase + ty * 8 + i;
            float4 c0 = {acc[i][0], acc[i][1], acc[i][2], acc[i][3]};
            float4 c1 = {acc[i][4], acc[i][5], acc[i][6], acc[i][7]};
            *(float4*)&d_SC[(size_t)row * 256 + ysel * 128 + tx * 8]     = c0;
            *(float4*)&d_SC[(size_t)row * 256 + ysel * 128 + tx * 8 + 4] = c1;
        }
    }
}

// ---------------------------------------------------------------------------
// Stats: [0,2048) layer-0 virtual-y0 stats; [2048,2560) SC stats (layer 3).
// ---------------------------------------------------------------------------
__global__ void __launch_bounds__(256) stats_kernel() {
    if (blockIdx.x < 2048) {
        const uint4* A4 = (const uint4*)d_Ah;
        const uint4* B4 = (const uint4*)d_Bh;
        __shared__ float ssum[128], ssq[128];
        if (threadIdx.x < 128) { ssum[threadIdx.x] = 0.f; ssq[threadIdx.x] = 0.f; }
        __syncthreads();
        const int start = blockIdx.x * 256 + threadIdx.x;
        const int c8 = start & 15;
        float s[8], q[8];
#pragma unroll
        for (int j = 0; j < 8; j++) { s[j] = 0.f; q[j] = 0.f; }
#pragma unroll 4
        for (int i = 0; i < 16; i++) {
            int e = start + i * 524288;
            int r = e >> 4, cc = e & 15;
            int np = r >> 4, n = r >> 14;
            int id = __ldg(&d_idx[r]);
            uint4 a = A4[(size_t)np * 16 + cc];
            uint4 b = B4[((size_t)n * 1024 + id) * 16 + cc];
            uint32_t aw[4] = {a.x, a.y, a.z, a.w};
            uint32_t bw[4] = {b.x, b.y, b.z, b.w};
#pragma unroll
            for (int j = 0; j < 4; j++) {
                float2 fa = __half22float2(*(__half2*)&aw[j]);
                float2 fb = __half22float2(*(__half2*)&bw[j]);
                float y0 = fa.x + fb.x, y1 = fa.y + fb.y;
                s[j * 2]     += y0; q[j * 2]     += y0 * y0;
                s[j * 2 + 1] += y1; q[j * 2 + 1] += y1 * y1;
            }
        }
#pragma unroll
        for (int j = 0; j < 8; j++) {
            atomicAdd(&ssum[c8 * 8 + j], s[j]);
            atomicAdd(&ssq [c8 * 8 + j], q[j]);
        }
        __syncthreads();
        if (threadIdx.x < 128) {
            atomicAdd(&d_sum  [threadIdx.x], ssum[threadIdx.x]);
            atomicAdd(&d_sumsq[threadIdx.x], ssq[threadIdx.x]);
        }
    } else {
        int b = blockIdx.x - 2048;
        int c = threadIdx.x;
        const float* base = d_SC + (size_t)b * 64 * 256 + c;
        float s = 0.f, q = 0.f;
#pragma unroll 8
        for (int r = 0; r < 64; r++) {
            float v = base[(size_t)r * 256];
            s += v; q += v * v;
        }
        atomicAdd(&d_sum  [3 * 256 + c], s);
        atomicAdd(&d_sumsq[3 * 256 + c], q);
    }
}

// ---------------------------------------------------------------------------
// Layer-1 MMA: gather+BN0+lrelu -> y1 fp16 + BN1 stats.
// ---------------------------------------------------------------------------
__global__ void __launch_bounds__(256, 2) gemm_mma1_kernel(
    const uint32_t* __restrict__ Wt, __half* __restrict__ Y,
    const float* __restrict__ g, const float* __restrict__ b) {
    extern __shared__ char smem_raw[];
    uint32_t* As = (uint32_t*)smem_raw;                    // [128][KW]
    uint32_t* Bs = As + 128 * KW;                          // [128][KW]
    float*  ssum = (float*)(Bs + 128 * KW);
    float*  ssq  = ssum + 128;
    float*  scs  = ssq + 128;
    float*  shs  = scs + 128;

    const int tid = threadIdx.x;
    const int wid = tid >> 5;
    const int lane = tid & 31;
    const int gid = lane >> 2;
    const int tg  = lane & 3;
    const int warpRow = wid & 3;
    const int warpCol = wid >> 2;
    const int tileBase = blockIdx.x * 128;

    if (tid < 128) {
        float mean = d_sum[tid] * (1.0f / (float)ROWS);
        float var  = d_sumsq[tid] * (1.0f / (float)ROWS) - mean * mean;
        float sc = g[tid] * rsqrtf(var + BN_EPS);
        scs[tid] = sc;
        shs[tid] = b[tid] - mean * sc;
        ssum[tid] = 0.f; ssq[tid] = 0.f;
    }
    __syncthreads();

    {
        const uint4* src = (const uint4*)Wt;
#pragma unroll
        for (int i = 0; i < 8; i++) {
            int e4 = tid + i * 256;
            int n = e4 >> 4, kw4 = e4 & 15;
            *(uint4*)&Bs[n * KW + kw4 * 4] = src[e4];
        }
    }
    int ids[8];
#pragma unroll
    for (int i = 0; i < 8; i++) {
        int r = (tid + i * 256) >> 4;
        ids[i] = __ldg(&d_idx[tileBase + r]);
    }
#pragma unroll
    for (int i = 0; i < 8; i++) {
        int e = tid + i * 256;
        int r = e >> 4, cw = e & 15;
        int R = tileBase + r;
        int np = R >> 4, n = R >> 14;
        uint4 ha = ((const uint4*)d_Ah)[(size_t)np * 16 + cw];
        uint4 hb = ((const uint4*)d_Bh)[((size_t)n * 1024 + ids[i]) * 16 + cw];
        uint32_t aw[4] = {ha.x, ha.y, ha.z, ha.w};
        uint32_t bw[4] = {hb.x, hb.y, hb.z, hb.w};
        float x[8];
#pragma unroll
        for (int j = 0; j < 4; j++) {
            float2 fa = __half22float2(*(__half2*)&aw[j]);
            float2 fb = __half22float2(*(__half2*)&bw[j]);
            x[j * 2] = fa.x + fb.x; x[j * 2 + 1] = fa.y + fb.y;
        }
        const float* sc = &scs[cw * 8];
        const float* sh = &shs[cw * 8];
        float y[8];
#pragma unroll
        for (int j = 0; j < 8; j++) y[j] = lrelu(x[j] * sc[j] + sh[j]);
        uint4 v;
        v.x = pack_h2(y[0], y[1]); v.y = pack_h2(y[2], y[3]);
        v.z = pack_h2(y[4], y[5]); v.w = pack_h2(y[6], y[7]);
        *(uint4*)&As[r * KW + cw * 4] = v;
    }
    __syncthreads();

    const int t8 = lane >> 3, r8 = lane & 7;
    uint32_t aAddr[2], bAddr[4];
#pragma unroll
    for (int mi = 0; mi < 2; mi++) {
        int row = warpRow * 32 + mi * 16 + (t8 & 1) * 8 + r8;
        aAddr[mi] = smem_u32(&As[row * KW + (t8 >> 1) * 4]);
    }
#pragma unroll
    for (int nj = 0; nj < 4; nj++) {
        int row = warpCol * 64 + nj * 16 + (t8 >> 1) * 8 + r8;
        bAddr[nj] = smem_u32(&Bs[row * KW + (t8 & 1) * 4]);
    }

    float c[2][8][4];
#pragma unroll
    for (int mi = 0; mi < 2; mi++)
#pragma unroll
        for (int ni = 0; ni < 8; ni++)
#pragma unroll
            for (int j = 0; j < 4; j++) c[mi][ni][j] = 0.f;
#pragma unroll
    for (int k0 = 0; k0 < 8; k0++) {
        uint32_t af[2][4], bf[4][4];
#pragma unroll
        for (int mi = 0; mi < 2; mi++) ldmatrix_x4(af[mi], aAddr[mi] + k0 * 32);
#pragma unroll
        for (int nj = 0; nj < 4; nj++) ldmatrix_x4(bf[nj], bAddr[nj] + k0 * 32);
#pragma unroll
        for (int mi = 0; mi < 2; mi++)
#pragma unroll
            for (int nj = 0; nj < 4; nj++) {
                mma_f16(c[mi][nj * 2],     af[mi], &bf[nj][0]);
                mma_f16(c[mi][nj * 2 + 1], af[mi], &bf[nj][2]);
            }
    }
#pragma unroll
    for (int mi = 0; mi < 2; mi++) {
        size_t r0 = (size_t)tileBase + warpRow * 32 + mi * 16 + gid;
#pragma unroll
        for (int ni = 0; ni < 8; ni++) {
            int col = warpCol * 64 + ni * 8 + tg * 2;
            __half2 v0 = __floats2half2_rn(c[mi][ni][0], c[mi][ni][1]);
            __half2 v1 = __floats2half2_rn(c[mi][ni][2], c[mi][ni][3]);
            *(__half2*)&Y[ r0      * 128 + col] = v0;
            *(__half2*)&Y[(r0 + 8) * 128 + col] = v1;
        }
    }
#pragma unroll
    for (int ni = 0; ni < 8; ni++) {
#pragma unroll
        for (int j = 0; j < 2; j++) {
            float s = c[0][ni][j] + c[0][ni][j + 2] + c[1][ni][j] + c[1][ni][j + 2];
            float q = c[0][ni][j]     * c[0][ni][j]
                    + c[0][ni][j + 2] * c[0][ni][j + 2]
                    + c[1][ni][j]     * c[1][ni][j]
                    + c[1][ni][j + 2] * c[1][ni][j + 2];
#pragma unroll
            for (int m = 16; m >= 4; m >>= 1) {
                s += __shfl_xor_sync(0xffffffffu, s, m);
                q += __shfl_xor_sync(0xffffffffu, q, m);
            }
            if (lane < 4) {
                int cch = warpCol * 64 + ni * 8 + tg * 2 + j;
                atomicAdd(&ssum[cch], s);
                atomicAdd(&ssq [cch], q);
            }
        }
    }
    __syncthreads();
    if (tid < 128) {
        atomicAdd(&d_sum  [256 + tid], ssum[tid]);
        atomicAdd(&d_sumsq[256 + tid], ssq[tid]);
    }
}

// ---------------------------------------------------------------------------
// Gram kernel (double-buffered): G = X2^T X2, xsum = sum_rows X2,
// X2 = fp16(lrelu(BN1(y1))). 256 CTAs x 16 tiles. One barrier per tile:
// produce(t+1 -> buf^1) overlaps other warps' MMA(t -> buf).
// ---------------------------------------------------------------------------
__global__ void __launch_bounds__(256, 2) gram_kernel(
    const float* __restrict__ g, const float* __restrict__ b) {
    extern __shared__ char smem_raw[];
    uint32_t* As = (uint32_t*)smem_raw;                    // [2][128*KW]
    float* scs  = (float*)(As + 2 * 128 * KW);             // [128]
    float* shs  = scs + 128;                               // [128]
    float* ssum = shs + 128;                               // [128]

    const int tid = threadIdx.x;
    const int wid = tid >> 5;
    const int lane = tid & 31;
    const int gid = lane >> 2;
    const int tg  = lane & 3;
    const int warpRow = wid & 3;
    const int warpCol = wid >> 2;
    const int t8 = lane >> 3, r8 = lane & 7;
    const int cw = tid & 15;

    if (tid < 128) {
        float mean = d_sum[256 + tid] * (1.0f / (float)ROWS);
        float var  = d_sumsq[256 + tid] * (1.0f / (float)ROWS) - mean * mean;
        float sc = g[tid] * rsqrtf(var + BN_EPS);
        scs[tid] = sc;
        shs[tid] = b[tid] - mean * sc;
        ssum[tid] = 0.f;
    }
    __syncthreads();

    uint32_t base = smem_u32(As);
    uint32_t aT[2], bT[4];
#pragma unroll
    for (int mi = 0; mi < 2; mi++) {
        int mbase = warpRow * 32 + mi * 16 + (t8 & 1) * 8;
        aT[mi] = base + (uint32_t)(((t8 >> 1) * 8 + r8) * KW4) + (uint32_t)(mbase * 2);
    }
#pragma unroll
    for (int nj = 0; nj < 4; nj++) {
        int nbase = warpCol * 64 + nj * 16 + (t8 >> 1) * 8;
        bT[nj] = base + (uint32_t)(((t8 & 1) * 8 + r8) * KW4) + (uint32_t)(nbase * 2);
    }

    float c[2][8][4];
#pragma unroll
    for (int mi = 0; mi < 2; mi++)
#pragma unroll
        for (int ni = 0; ni < 8; ni++)
#pragma unroll
            for (int j = 0; j < 4; j++) c[mi][ni][j] = 0.f;
    float xs[8];
#pragma unroll
    for (int j = 0; j < 8; j++) xs[j] = 0.f;

    // produce tile into buffer buf: x2 = fp16(lrelu(BN1(y1))) + xsum accum
    auto produce = [&](int t, int buf) {
        int rowBase = blockIdx.x * 2048 + t * 128;
        uint32_t* dst = As + buf * 128 * KW;
#pragma unroll
        for (int i = 0; i < 8; i++) {
            int e = tid + i * 256;
            int r = e >> 4;
            uint4 h = ((const uint4*)&d_y1[(size_t)(rowBase + r) * 128])[cw];
            uint32_t hw[4] = {h.x, h.y, h.z, h.w};
            const float* sc = &scs[cw * 8];
            const float* sh = &shs[cw * 8];
            float y[8];
#pragma unroll
            for (int j = 0; j < 4; j++) {
                float2 f = __half22float2(*(__half2*)&hw[j]);
                y[j * 2]     = lrelu(f.x * sc[j * 2]     + sh[j * 2]);
                y[j * 2 + 1] = lrelu(f.y * sc[j * 2 + 1] + sh[j * 2 + 1]);
            }
            uint4 v;
            v.x = pack_h2(y[0], y[1]); v.y = pack_h2(y[2], y[3]);
            v.z = pack_h2(y[4], y[5]); v.w = pack_h2(y[6], y[7]);
            uint32_t vv[4] = {v.x, v.y, v.z, v.w};
#pragma unroll
            for (int j = 0; j < 4; j++) {
                float2 f = __half22float2(*(__half2*)&vv[j]);
                xs[j * 2] += f.x; xs[j * 2 + 1] += f.y;
            }
            *(uint4*)&dst[r * KW + cw * 4] = v;
        }
    };

    produce(0, 0);
    __syncthreads();
    for (int t = 0; t < 16; t++) {
        int buf = t & 1;
        if (t < 15) produce(t + 1, buf ^ 1);   // LDGs overlap other warps' MMA
        uint32_t bufOff = (uint32_t)(buf * 128 * KW4);
#pragma unroll
        for (int k0 = 0; k0 < 8; k0++) {
            uint32_t off = bufOff + (uint32_t)(k0 * 16 * KW4);
            uint32_t af[2][4], bf[4][4];
#pragma unroll
            for (int mi = 0; mi < 2; mi++) ldmatrix_x4_trans(af[mi], aT[mi] + off);
#pragma unroll
            for (int nj = 0; nj < 4; nj++) ldmatrix_x4_trans(bf[nj], bT[nj] + off);
#pragma unroll
            for (int mi = 0; mi < 2; mi++)
#pragma unroll
                for (int nj = 0; nj < 4; nj++) {
                    mma_f16(c[mi][nj * 2],     af[mi], &bf[nj][0]);
                    mma_f16(c[mi][nj * 2 + 1], af[mi], &bf[nj][2]);
                }
        }
        __syncthreads();
    }

#pragma unroll
    for (int mi = 0; mi < 2; mi++) {
        int m0 = warpRow * 32 + mi * 16 + gid;
#pragma unroll
        for (int ni = 0; ni < 8; ni++) {
            int n0 = warpCol * 64 + ni * 8 + tg * 2;
            atomicAdd(&d_gram[ m0      * 128 + n0    ], c[mi][ni][0]);
            atomicAdd(&d_gram[ m0      * 128 + n0 + 1], c[mi][ni][1]);
            atomicAdd(&d_gram[(m0 + 8) * 128 + n0    ], c[mi][ni][2]);
            atomicAdd(&d_gram[(m0 + 8) * 128 + n0 + 1], c[mi][ni][3]);
        }
    }
#pragma unroll
    for (int j = 0; j < 8; j++) atomicAdd(&ssum[cw * 8 + j], xs[j]);
    __syncthreads();
    if (tid < 128) atomicAdd(&d_xsum[tid], ssum[tid]);
}

// ---------------------------------------------------------------------------
// BN2 prep: per channel c, sum = xsum.w_c ; sumsq = w_c^T G w_c.
// ---------------------------------------------------------------------------
__global__ void __launch_bounds__(128) bn2_prep_kernel() {
    const int c = blockIdx.x;
    const int tid = threadIdx.x;
    __shared__ float w[128];
    __shared__ float red[8];
    if (tid < 64) {
        uint32_t p = d_W2t[c * 64 + tid];
        float2 f = __half22float2(*(__half2*)&p);
        w[2 * tid] = f.x; w[2 * tid + 1] = f.y;
    }
    __syncthreads();
    float wj = w[tid];
    float v = 0.f;
#pragma unroll 8
    for (int i = 0; i < 128; i++) v += w[i] * d_gram[i * 128 + tid];
    float q = wj * v;
    float s = wj * d_xsum[tid];
#pragma unroll
    for (int m = 16; m >= 1; m >>= 1) {
        q += __shfl_xor_sync(0xffffffffu, q, m);
        s += __shfl_xor_sync(0xffffffffu, s, m);
    }
    if ((tid & 31) == 0) { red[(tid >> 5) * 2] = q; red[(tid >> 5) * 2 + 1] = s; }
    __syncthreads();
    if (tid == 0) {
        d_sumsq[512 + c] = red[0] + red[2] + red[4] + red[6];
        d_sum  [512 + c] = red[1] + red[3] + red[5] + red[7];
    }
}

// ---------------------------------------------------------------------------
// Layer-2 MMA + fused k-mean + shortcut + final lrelu -> out (no y2).
// ---------------------------------------------------------------------------
__global__ void __launch_bounds__(256, 2) mma2_out_kernel(
    const float* __restrict__ g1, const float* __restrict__ b1,
    const float* __restrict__ g2, const float* __restrict__ b2,
    const float* __restrict__ gsc, const float* __restrict__ bsc,
    float* __restrict__ out) {
    extern __shared__ char smem_raw[];
    uint32_t* As = (uint32_t*)smem_raw;                    // [128][KW]
    uint32_t* Bs = As + 128 * KW;                          // [128][KW]
    float* fts = (float*)(Bs + 128 * KW);                  // [8][256]
    float* scs = fts + 8 * 256;                            // [128]
    float* shs = scs + 128;                                // [128]
    float* s2s = shs + 128;                                // [256]
    float* h2s = s2s + 256;                                // [256]
    float* s3s = h2s + 256;                                // [256]
    float* h3s = s3s + 256;                                // [256]

    const int tid = threadIdx.x;
    const int wid = tid >> 5;
    const int lane = tid & 31;
    const int tg  = lane & 3;
    const int warpRow = wid & 3;
    const int warpCol = wid >> 2;
    const int tileBase = blockIdx.x * 128;

    if (tid < 128) {
        float mean = d_sum[256 + tid] * (1.0f / (float)ROWS);
        float var  = d_sumsq[256 + tid] * (1.0f / (float)ROWS) - mean * mean;
        float sc = g1[tid] * rsqrtf(var + BN_EPS);
        scs[tid] = sc;
        shs[tid] = b1[tid] - mean * sc;
    }
    {
        int cch = tid;
        float mean2 = d_sum[512 + cch] * (1.0f / (float)ROWS);
        float var2  = d_sumsq[512 + cch] * (1.0f / (float)ROWS) - mean2 * mean2;
        float sc2 = g2[cch] * rsqrtf(var2 + BN_EPS);
        s2s[cch] = sc2; h2s[cch] = b2[cch] - mean2 * sc2;
        float mean3 = d_sum[768 + cch] * (1.0f / (float)NPTS);
        float var3  = d_sumsq[768 + cch] * (1.0f / (float)NPTS) - mean3 * mean3;
        float sc3 = gsc[cch] * rsqrtf(var3 + BN_EPS);
        s3s[cch] = sc3; h3s[cch] = bsc[cch] - mean3 * sc3;
    }
    __syncthreads();

#pragma unroll
    for (int i = 0; i < 8; i++) {
        int e = tid + i * 256;
        int r = e >> 4, cw = e & 15;
        uint4 h = ((const uint4*)&d_y1[(size_t)(tileBase + r) * 128])[cw];
        uint32_t hw[4] = {h.x, h.y, h.z, h.w};
        const float* sc = &scs[cw * 8];
        const float* sh = &shs[cw * 8];
        float y[8];
#pragma unroll
        for (int j = 0; j < 4; j++) {
            float2 f = __half22float2(*(__half2*)&hw[j]);
            y[j * 2]     = lrelu(f.x * sc[j * 2]     + sh[j * 2]);
            y[j * 2 + 1] = lrelu(f.y * sc[j * 2 + 1] + sh[j * 2 + 1]);
        }
        uint4 v;
        v.x = pack_h2(y[0], y[1]); v.y = pack_h2(y[2], y[3]);
        v.z = pack_h2(y[4], y[5]); v.w = pack_h2(y[6], y[7]);
        *(uint4*)&As[r * KW + cw * 4] = v;
    }
    {
        const uint4* src = (const uint4*)d_W2t;
#pragma unroll
        for (int i = 0; i < 8; i++) {
            int e4 = tid + i * 256;
            int n = e4 >> 4, kw4 = e4 & 15;
            *(uint4*)&Bs[n * KW + kw4 * 4] = src[e4];
        }
    }
    __syncthreads();

    const int t8 = lane >> 3, r8 = lane & 7;
    uint32_t aAddr[2], bAddr[4];
#pragma unroll
    for (int mi = 0; mi < 2; mi++) {
        int row = warpRow * 32 + mi * 16 + (t8 & 1) * 8 + r8;
        aAddr[mi] = smem_u32(&As[row * KW + (t8 >> 1) * 4]);
    }
#pragma unroll
    for (int nj = 0; nj < 4; nj++) {
        int row = warpCol * 64 + nj * 16 + (t8 >> 1) * 8 + r8;
        bAddr[nj] = smem_u32(&Bs[row * KW + (t8 & 1) * 4]);
    }

#pragma unroll
    for (int h = 0; h < 2; h++) {
        if (h == 1) {
            __syncthreads();
            const uint4* src = (const uint4*)d_W2t + 2048;
#pragma unroll
            for (int i = 0; i < 8; i++) {
                int e4 = tid + i * 256;
                int n = e4 >> 4, kw4 = e4 & 15;
                *(uint4*)&Bs[n * KW + kw4 * 4] = src[e4];
            }
            __syncthreads();
        }
        float c[2][8][4];
#pragma unroll
        for (int mi = 0; mi < 2; mi++)
#pragma unroll
            for (int ni = 0; ni < 8; ni++)
#pragma unroll
                for (int j = 0; j < 4; j++) c[mi][ni][j] = 0.f;
#pragma unroll
        for (int k0 = 0; k0 < 8; k0++) {
            uint32_t af[2][4], bf[4][4];
#pragma unroll
            for (int mi = 0; mi < 2; mi++) ldmatrix_x4(af[mi], aAddr[mi] + k0 * 32);
#pragma unroll
            for (int nj = 0; nj < 4; nj++) ldmatrix_x4(bf[nj], bAddr[nj] + k0 * 32);
#pragma unroll
            for (int mi = 0; mi < 2; mi++)
#pragma unroll
                for (int nj = 0; nj < 4; nj++) {
                    mma_f16(c[mi][nj * 2],     af[mi], &bf[nj][0]);
                    mma_f16(c[mi][nj * 2 + 1], af[mi], &bf[nj][2]);
                }
        }
#pragma unroll
        for (int mi = 0; mi < 2; mi++) {
            int npL = warpRow * 2 + mi;
#pragma unroll
            for (int ni = 0; ni < 8; ni++) {
#pragma unroll
                for (int j = 0; j < 2; j++) {
                    int cch = h * 128 + warpCol * 64 + ni * 8 + tg * 2 + j;
                    float sv = s2s[cch], hv = h2s[cch];
                    float p = lrelu(c[mi][ni][j] * sv + hv)
                            + lrelu(c[mi][ni][j + 2] * sv + hv);
#pragma unroll
                    for (int m = 16; m >= 4; m >>= 1)
                        p += __shfl_xor_sync(0xffffffffu, p, m);
                    if (lane < 4) fts[npL * 256 + cch] = p;
                }
            }
        }
    }
    __syncthreads();

    const int npBase = blockIdx.x * 8;
#pragma unroll
    for (int i = 0; i < 2; i++) {
        int e4 = tid + i * 256;
        int npL = e4 >> 6, c4 = e4 & 63;
        float4 sc = ((const float4*)d_SC)[(size_t)(npBase + npL) * 64 + c4];
        float4 f  = ((const float4*)fts)[npL * 64 + c4];
        const float inv = 1.0f / 16.0f;
        float4 o;
        o.x = lrelu(sc.x * s3s[c4 * 4 + 0] + h3s[c4 * 4 + 0] + f.x * inv);
        o.y = lrelu(sc.y * s3s[c4 * 4 + 1] + h3s[c4 * 4 + 1] + f.y * inv);
        o.z = lrelu(sc.z * s3s[c4 * 4 + 2] + h3s[c4 * 4 + 2] + f.z * inv);
        o.w = lrelu(sc.w * s3s[c4 * 4 + 3] + h3s[c4 * 4 + 3] + f.w * inv);
        ((float4*)out)[(size_t)(npBase + npL) * 64 + c4] = o;
    }
}

// ---------------------------------------------------------------------------
// Launch (6 launches; gram at idx 3 -> ncu abs index 5)
// ---------------------------------------------------------------------------
extern "C" void kernel_launch(void* const* d_in, const int* in_sizes, int n_in,
                              void* d_out, int out_size) {
    const float* points   = (const float*)d_in[0];
    const float* features = (const float*)d_in[1];
    const float* W0  = (const float*)d_in[2];
    const float* g0  = (const float*)d_in[3];
    const float* b0  = (const float*)d_in[4];
    const float* W1  = (const float*)d_in[5];
    const float* g1  = (const float*)d_in[6];
    const float* b1  = (const float*)d_in[7];
    const float* W2  = (const float*)d_in[8];
    const float* g2  = (const float*)d_in[9];
    const float* b2  = (const float*)d_in[10];
    const float* Wsc = (const float*)d_in[11];
    const float* gsc = (const float*)d_in[12];
    const float* bsc = (const float*)d_in[13];
    float* out = (float*)d_out;

    __half* p1;
    uint32_t* pW1t;
    cudaGetSymbolAddress((void**)&p1,  d_y1);
    cudaGetSymbolAddress((void**)&pW1t, d_W1t);

    constexpr int SMEM_MMA1 = (2 * 128 * KW) * 4 + 4 * 128 * 4;
    constexpr int SMEM_GRAM = (2 * 128 * KW) * 4 + 3 * 128 * 4;
    constexpr int SMEM_OUT  = (2 * 128 * KW) * 4 + 8 * 256 * 4 + (2 * 128 + 4 * 256) * 4;
    cudaFuncSetAttribute(gemm_mma1_kernel,
                         cudaFuncAttributeMaxDynamicSharedMemorySize, SMEM_MMA1);
    cudaFuncSetAttribute(gram_kernel,
                         cudaFuncAttributeMaxDynamicSharedMemorySize, SMEM_GRAM);
    cudaFuncSetAttribute(mma2_out_kernel,
                         cudaFuncAttributeMaxDynamicSharedMemorySize, SMEM_OUT);

    // 0: mega setup
    mega_kernel<<<1152, 256>>>(points, features, W0, Wsc, W1, W2);
    // 1: layer-0 virtual-y0 stats + SC stats
    stats_kernel<<<2560, 256>>>();
    // 2: layer-1 MMA -> y1 + BN1 stats
    gemm_mma1_kernel<<<ROWS / 128, 256, SMEM_MMA1>>>(pW1t, p1, g0, b0);
    // 3: Gram of x2 + xsum (tensor syrk, double-buffered)  [PROFILED]
    gram_kernel<<<256, 256, SMEM_GRAM>>>(g1, b1);
    // 4: BN2 stats from Gram
    bn2_prep_kernel<<<256, 128>>>();
    // 5: layer-2 MMA + k-mean + shortcut + out
    mma2_out_kernel<<<ROWS / 128, 256, SMEM_OUT>>>(g1, b1, g2, b2, gsc, bsc, out);
}

// round 17
// speedup vs baseline: 1.4744x; 1.1709x over previous
#include <cuda_runtime.h>
#include <cuda_fp16.h>
#include <math.h>
#include <cstdint>

#define NB   32
#define PP   1024
#define KNN  16
#define NPTS (NB * PP)       // 32768
#define ROWS (NPTS * KNN)    // 524288
#define LRELU_ALPHA 0.1f
#define BN_EPS 1e-3f
#define KW 68
#define KW4 (KW * 4)
#define KW2 36               // K=64 setup GEMM row stride (words)

// ---------------------------------------------------------------------------
// Static device scratch
// ---------------------------------------------------------------------------
__device__ __half d_Ah [NPTS * 128];
__device__ __half d_Bh [NPTS * 128];
__device__ float  d_SC [NPTS * 256];
__device__ __half d_y1 [ROWS * 128];
__device__ int    d_idx [ROWS];
__device__ uint32_t d_W1t[128 * 64];
__device__ uint32_t d_W2t[256 * 64];
__device__ float  d_sum  [4 * 256];
__device__ float  d_sumsq[4 * 256];
__device__ float  d_gram [128 * 128];
__device__ float  d_xsum [128];

__device__ __forceinline__ void mma_f16(float* d, const uint32_t* a, const uint32_t* b) {
    asm volatile(
        "mma.sync.aligned.m16n8k16.row.col.f32.f16.f16.f32 "
        "{%0,%1,%2,%3}, {%4,%5,%6,%7}, {%8,%9}, {%0,%1,%2,%3};"
        : "+f"(d[0]), "+f"(d[1]), "+f"(d[2]), "+f"(d[3])
        : "r"(a[0]), "r"(a[1]), "r"(a[2]), "r"(a[3]), "r"(b[0]), "r"(b[1]));
}
__device__ __forceinline__ void ldmatrix_x4(uint32_t* r, uint32_t addr) {
    asm volatile("ldmatrix.sync.aligned.m8n8.x4.shared.b16 {%0,%1,%2,%3}, [%4];"
                 : "=r"(r[0]), "=r"(r[1]), "=r"(r[2]), "=r"(r[3]) : "r"(addr));
}
__device__ __forceinline__ void ldmatrix_x4_trans(uint32_t* r, uint32_t addr) {
    asm volatile("ldmatrix.sync.aligned.m8n8.x4.trans.shared.b16 {%0,%1,%2,%3}, [%4];"
                 : "=r"(r[0]), "=r"(r[1]), "=r"(r[2]), "=r"(r[3]) : "r"(addr));
}
__device__ __forceinline__ uint32_t smem_u32(const void* p) {
    uint32_t a;
    asm("{ .reg .u64 t; cvta.to.shared.u64 t, %1; cvt.u32.u64 %0, t; }" : "=r"(a) : "l"(p));
    return a;
}
__device__ __forceinline__ uint32_t pack_h2(float lo, float hi) {
    __half2 h = __floats2half2_rn(lo, hi);
    return *(uint32_t*)&h;
}
__device__ __forceinline__ float lrelu(float x) {
    return x > 0.f ? x : LRELU_ALPHA * x;
}

// ---------------------------------------------------------------------------
// MEGA setup: [0,128) KNN (register top-16) + side duties;
// [128,384): dual tensor GEMM [A|B] fp16; [384,640): SC tensor GEMM fp32.
// Tensor GEMMs: BM=128, K=64 (4 k16-steps), N=256 via two 128 halves.
// ---------------------------------------------------------------------------
__global__ void __launch_bounds__(256) mega_kernel(
    const float* __restrict__ pts, const float* __restrict__ feat,
    const float* __restrict__ W0,  const float* __restrict__ Wsc,
    const float* __restrict__ W1,  const float* __restrict__ W2) {
    extern __shared__ char smem_raw[];
    const int bid = blockIdx.x;
    const int tid = threadIdx.x;

    if (bid < 128) {
        // ---- side duties -------------------------------------------------
        if (bid < 64) d_gram[bid * 256 + tid] = 0.f;
        if (bid == 64) {
            for (int i = tid; i < 1024; i += 256) { d_sum[i] = 0.f; d_sumsq[i] = 0.f; }
            if (tid < 128) d_xsum[tid] = 0.f;
        } else if (bid == 65) {
            for (int t = tid; t < 128 * 64; t += 256) {
                int n = t >> 6, kw = t & 63;
                d_W1t[t] = pack_h2(W1[(size_t)(2 * kw) * 128 + n],
                                   W1[(size_t)(2 * kw + 1) * 128 + n]);
            }
        } else if (bid == 66 || bid == 67) {
            int base = (bid - 66) * 8192;
            for (int i = tid; i < 8192; i += 256) {
                int t = base + i;
                int n = t >> 6, kw = t & 63;
                d_W2t[t] = pack_h2(W2[(size_t)(2 * kw) * 256 + n],
                                   W2[(size_t)(2 * kw + 1) * 256 + n]);
            }
        }
        // ---- knn (register-resident) --------------------------------------
        float* sx = (float*)smem_raw;
        float* sy = sx + 1024;
        float* sz = sy + 1024;
        int n = bid >> 2;
        int p = ((bid & 3) << 8) + tid;
        const float* base = pts + (size_t)n * PP * 3;
        for (int i = tid; i < PP; i += 256) {
            sx[i] = base[i * 3 + 0];
            sy[i] = base[i * 3 + 1];
            sz[i] = base[i * 3 + 2];
        }
        __syncthreads();
        float qx = sx[p], qy = sy[p], qz = sz[p];
        float bd[KNN]; int bi[KNN];
#pragma unroll
        for (int i = 0; i < KNN; i++) { bd[i] = 3.0e38f; bi[i] = 0; }
        for (int q = 0; q < PP; q++) {
            float dx = sx[q] - qx, dy = sy[q] - qy, dz = sz[q] - qz;
            float d = dx * dx + dy * dy + dz * dz;
            if (q == p) continue;
            if (d < bd[KNN - 1]) {
                float cd = d; int ci = q;
#pragma unroll
                for (int j = 0; j < KNN; j++) {
                    if (cd < bd[j]) {
                        float td = bd[j]; int ti = bi[j];
                        bd[j] = cd; bi[j] = ci;
                        cd = td; ci = ti;
                    }
                }
            }
        }
        int ob = (n * PP + p) * KNN;
#pragma unroll
        for (int k = 0; k < KNN; k++) d_idx[ob + k] = bi[k];
        return;
    }

    // ---- tensor setup GEMM --------------------------------------------------
    const int sub = bid - 128;            // 0..511
    const bool isSC = sub >= 256;
    const int rowBase = (sub & 255) * 128;
    uint32_t* As = (uint32_t*)smem_raw;         // [128][KW2]
    uint32_t* Bs = As + 128 * KW2;              // [256][KW2]

    const int wid = tid >> 5;
    const int lane = tid & 31;
    const int gid = lane >> 2;
    const int tg  = lane & 3;
    const int warpRow = wid & 3;
    const int warpCol = wid >> 2;

    // B tile fill from fp32 weights (coalesced in n)
    for (int e = tid; e < 8192; e += 256) {
        int kw = e >> 8, n = e & 255;
        float v0, v1;
        if (!isSC) {
            if (n < 128) {
                v0 = W0[(size_t)(2 * kw) * 128 + n]     - W0[(size_t)(64 + 2 * kw) * 128 + n];
                v1 = W0[(size_t)(2 * kw + 1) * 128 + n] - W0[(size_t)(65 + 2 * kw) * 128 + n];
            } else {
                v0 = W0[(size_t)(64 + 2 * kw) * 128 + n - 128];
                v1 = W0[(size_t)(65 + 2 * kw) * 128 + n - 128];
            }
        } else {
            v0 = Wsc[(size_t)(2 * kw) * 256 + n];
            v1 = Wsc[(size_t)(2 * kw + 1) * 256 + n];
        }
        Bs[n * KW2 + kw] = pack_h2(v0, v1);
    }
    // A tile: features fp32 -> fp16
#pragma unroll
    for (int i = 0; i < 4; i++) {
        int e = tid + i * 256;                 // 0..1023
        int r = e >> 3, q = e & 7;             // 8 uint4 per row
        const float4* src = (const float4*)&feat[(size_t)(rowBase + r) * 64 + q * 8];
        float4 f0 = src[0], f1 = src[1];
        uint4 v;
        v.x = pack_h2(f0.x, f0.y); v.y = pack_h2(f0.z, f0.w);
        v.z = pack_h2(f1.x, f1.y); v.w = pack_h2(f1.z, f1.w);
        *(uint4*)&As[r * KW2 + q * 4] = v;
    }
    __syncthreads();

    const int t8 = lane >> 3, r8 = lane & 7;
    uint32_t aAddr[2], bAddr[4];
#pragma unroll
    for (int mi = 0; mi < 2; mi++) {
        int row = warpRow * 32 + mi * 16 + (t8 & 1) * 8 + r8;
        aAddr[mi] = smem_u32(&As[row * KW2 + (t8 >> 1) * 4]);
    }
#pragma unroll
    for (int nj = 0; nj < 4; nj++) {
        int row = warpCol * 64 + nj * 16 + (t8 >> 1) * 8 + r8;
        bAddr[nj] = smem_u32(&Bs[row * KW2 + (t8 & 1) * 4]);
    }

#pragma unroll
    for (int h = 0; h < 2; h++) {
        const uint32_t bOff = (uint32_t)(h * 128 * KW2 * 4);
        float c[2][8][4];
#pragma unroll
        for (int mi = 0; mi < 2; mi++)
#pragma unroll
            for (int ni = 0; ni < 8; ni++)
#pragma unroll
                for (int j = 0; j < 4; j++) c[mi][ni][j] = 0.f;
#pragma unroll
        for (int k0 = 0; k0 < 4; k0++) {
            uint32_t af[2][4], bf[4][4];
#pragma unroll
            for (int mi = 0; mi < 2; mi++) ldmatrix_x4(af[mi], aAddr[mi] + k0 * 32);
#pragma unroll
            for (int nj = 0; nj < 4; nj++) ldmatrix_x4(bf[nj], bAddr[nj] + bOff + k0 * 32);
#pragma unroll
            for (int mi = 0; mi < 2; mi++)
#pragma unroll
                for (int nj = 0; nj < 4; nj++) {
                    mma_f16(c[mi][nj * 2],     af[mi], &bf[nj][0]);
                    mma_f16(c[mi][nj * 2 + 1], af[mi], &bf[nj][2]);
                }
        }
        if (!isSC) {
            __half* Yh = (h == 0) ? d_Ah : d_Bh;
#pragma unroll
            for (int mi = 0; mi < 2; mi++) {
                size_t r0 = (size_t)rowBase + warpRow * 32 + mi * 16 + gid;
#pragma unroll
                for (int ni = 0; ni < 8; ni++) {
                    int col = warpCol * 64 + ni * 8 + tg * 2;
                    __half2 v0 = __floats2half2_rn(c[mi][ni][0], c[mi][ni][1]);
                    __half2 v1 = __floats2half2_rn(c[mi][ni][2], c[mi][ni][3]);
                    *(__half2*)&Yh[ r0      * 128 + col] = v0;
                    *(__half2*)&Yh[(r0 + 8) * 128 + col] = v1;
                }
            }
        } else {
#pragma unroll
            for (int mi = 0; mi < 2; mi++) {
                size_t r0 = (size_t)rowBase + warpRow * 32 + mi * 16 + gid;
#pragma unroll
                for (int ni = 0; ni < 8; ni++) {
                    int col = h * 128 + warpCol * 64 + ni * 8 + tg * 2;
                    *(float2*)&d_SC[ r0      * 256 + col] = make_float2(c[mi][ni][0], c[mi][ni][1]);
                    *(float2*)&d_SC[(r0 + 8) * 256 + col] = make_float2(c[mi][ni][2], c[mi][ni][3]);
                }
            }
        }
    }
}

// ---------------------------------------------------------------------------
// Stats: [0,2048) layer-0 virtual-y0 stats; [2048,2560) SC stats (layer 3).
// ---------------------------------------------------------------------------
__global__ void __launch_bounds__(256) stats_kernel() {
    if (blockIdx.x < 2048) {
        const uint4* A4 = (const uint4*)d_Ah;
        const uint4* B4 = (const uint4*)d_Bh;
        __shared__ float ssum[128], ssq[128];
        if (threadIdx.x < 128) { ssum[threadIdx.x] = 0.f; ssq[threadIdx.x] = 0.f; }
        __syncthreads();
        const int start = blockIdx.x * 256 + threadIdx.x;
        const int c8 = start & 15;
        float s[8], q[8];
#pragma unroll
        for (int j = 0; j < 8; j++) { s[j] = 0.f; q[j] = 0.f; }
#pragma unroll 4
        for (int i = 0; i < 16; i++) {
            int e = start + i * 524288;
            int r = e >> 4, cc = e & 15;
            int np = r >> 4, n = r >> 14;
            int id = __ldg(&d_idx[r]);
            uint4 a = A4[(size_t)np * 16 + cc];
            uint4 b = B4[((size_t)n * 1024 + id) * 16 + cc];
            uint32_t aw[4] = {a.x, a.y, a.z, a.w};
            uint32_t bw[4] = {b.x, b.y, b.z, b.w};
#pragma unroll
            for (int j = 0; j < 4; j++) {
                float2 fa = __half22float2(*(__half2*)&aw[j]);
                float2 fb = __half22float2(*(__half2*)&bw[j]);
                float y0 = fa.x + fb.x, y1 = fa.y + fb.y;
                s[j * 2]     += y0; q[j * 2]     += y0 * y0;
                s[j * 2 + 1] += y1; q[j * 2 + 1] += y1 * y1;
            }
        }
#pragma unroll
        for (int j = 0; j < 8; j++) {
            atomicAdd(&ssum[c8 * 8 + j], s[j]);
            atomicAdd(&ssq [c8 * 8 + j], q[j]);
        }
        __syncthreads();
        if (threadIdx.x < 128) {
            atomicAdd(&d_sum  [threadIdx.x], ssum[threadIdx.x]);
            atomicAdd(&d_sumsq[threadIdx.x], ssq[threadIdx.x]);
        }
    } else {
        int b = blockIdx.x - 2048;
        int c = threadIdx.x;
        const float* base = d_SC + (size_t)b * 64 * 256 + c;
        float s = 0.f, q = 0.f;
#pragma unroll 8
        for (int r = 0; r < 64; r++) {
            float v = base[(size_t)r * 256];
            s += v; q += v * v;
        }
        atomicAdd(&d_sum  [3 * 256 + c], s);
        atomicAdd(&d_sumsq[3 * 256 + c], q);
    }
}

// ---------------------------------------------------------------------------
// Layer-1 MMA: gather+BN0+lrelu -> y1 fp16 + BN1 stats.
// ---------------------------------------------------------------------------
__global__ void __launch_bounds__(256, 2) gemm_mma1_kernel(
    const uint32_t* __restrict__ Wt, __half* __restrict__ Y,
    const float* __restrict__ g, const float* __restrict__ b) {
    extern __shared__ char smem_raw[];
    uint32_t* As = (uint32_t*)smem_raw;                    // [128][KW]
    uint32_t* Bs = As + 128 * KW;                          // [128][KW]
    float*  ssum = (float*)(Bs + 128 * KW);
    float*  ssq  = ssum + 128;
    float*  scs  = ssq + 128;
    float*  shs  = scs + 128;

    const int tid = threadIdx.x;
    const int wid = tid >> 5;
    const int lane = tid & 31;
    const int gid = lane >> 2;
    const int tg  = lane & 3;
    const int warpRow = wid & 3;
    const int warpCol = wid >> 2;
    const int tileBase = blockIdx.x * 128;

    if (tid < 128) {
        float mean = d_sum[tid] * (1.0f / (float)ROWS);
        float var  = d_sumsq[tid] * (1.0f / (float)ROWS) - mean * mean;
        float sc = g[tid] * rsqrtf(var + BN_EPS);
        scs[tid] = sc;
        shs[tid] = b[tid] - mean * sc;
        ssum[tid] = 0.f; ssq[tid] = 0.f;
    }
    __syncthreads();

    {
        const uint4* src = (const uint4*)Wt;
#pragma unroll
        for (int i = 0; i < 8; i++) {
            int e4 = tid + i * 256;
            int n = e4 >> 4, kw4 = e4 & 15;
            *(uint4*)&Bs[n * KW + kw4 * 4] = src[e4];
        }
    }
    int ids[8];
#pragma unroll
    for (int i = 0; i < 8; i++) {
        int r = (tid + i * 256) >> 4;
        ids[i] = __ldg(&d_idx[tileBase + r]);
    }
#pragma unroll
    for (int i = 0; i < 8; i++) {
        int e = tid + i * 256;
        int r = e >> 4, cw = e & 15;
        int R = tileBase + r;
        int np = R >> 4, n = R >> 14;
        uint4 ha = ((const uint4*)d_Ah)[(size_t)np * 16 + cw];
        uint4 hb = ((const uint4*)d_Bh)[((size_t)n * 1024 + ids[i]) * 16 + cw];
        uint32_t aw[4] = {ha.x, ha.y, ha.z, ha.w};
        uint32_t bw[4] = {hb.x, hb.y, hb.z, hb.w};
        float x[8];
#pragma unroll
        for (int j = 0; j < 4; j++) {
            float2 fa = __half22float2(*(__half2*)&aw[j]);
            float2 fb = __half22float2(*(__half2*)&bw[j]);
            x[j * 2] = fa.x + fb.x; x[j * 2 + 1] = fa.y + fb.y;
        }
        const float* sc = &scs[cw * 8];
        const float* sh = &shs[cw * 8];
        float y[8];
#pragma unroll
        for (int j = 0; j < 8; j++) y[j] = lrelu(x[j] * sc[j] + sh[j]);
        uint4 v;
        v.x = pack_h2(y[0], y[1]); v.y = pack_h2(y[2], y[3]);
        v.z = pack_h2(y[4], y[5]); v.w = pack_h2(y[6], y[7]);
        *(uint4*)&As[r * KW + cw * 4] = v;
    }
    __syncthreads();

    const int t8 = lane >> 3, r8 = lane & 7;
    uint32_t aAddr[2], bAddr[4];
#pragma unroll
    for (int mi = 0; mi < 2; mi++) {
        int row = warpRow * 32 + mi * 16 + (t8 & 1) * 8 + r8;
        aAddr[mi] = smem_u32(&As[row * KW + (t8 >> 1) * 4]);
    }
#pragma unroll
    for (int nj = 0; nj < 4; nj++) {
        int row = warpCol * 64 + nj * 16 + (t8 >> 1) * 8 + r8;
        bAddr[nj] = smem_u32(&Bs[row * KW + (t8 & 1) * 4]);
    }

    float c[2][8][4];
#pragma unroll
    for (int mi = 0; mi < 2; mi++)
#pragma unroll
        for (int ni = 0; ni < 8; ni++)
#pragma unroll
            for (int j = 0; j < 4; j++) c[mi][ni][j] = 0.f;
#pragma unroll
    for (int k0 = 0; k0 < 8; k0++) {
        uint32_t af[2][4], bf[4][4];
#pragma unroll
        for (int mi = 0; mi < 2; mi++) ldmatrix_x4(af[mi], aAddr[mi] + k0 * 32);
#pragma unroll
        for (int nj = 0; nj < 4; nj++) ldmatrix_x4(bf[nj], bAddr[nj] + k0 * 32);
#pragma unroll
        for (int mi = 0; mi < 2; mi++)
#pragma unroll
            for (int nj = 0; nj < 4; nj++) {
                mma_f16(c[mi][nj * 2],     af[mi], &bf[nj][0]);
                mma_f16(c[mi][nj * 2 + 1], af[mi], &bf[nj][2]);
            }
    }
#pragma unroll
    for (int mi = 0; mi < 2; mi++) {
        size_t r0 = (size_t)tileBase + warpRow * 32 + mi * 16 + gid;
#pragma unroll
        for (int ni = 0; ni < 8; ni++) {
            int col = warpCol * 64 + ni * 8 + tg * 2;
            __half2 v0 = __floats2half2_rn(c[mi][ni][0], c[mi][ni][1]);
            __half2 v1 = __floats2half2_rn(c[mi][ni][2], c[mi][ni][3]);
            *(__half2*)&Y[ r0      * 128 + col] = v0;
            *(__half2*)&Y[(r0 + 8) * 128 + col] = v1;
        }
    }
#pragma unroll
    for (int ni = 0; ni < 8; ni++) {
#pragma unroll
        for (int j = 0; j < 2; j++) {
            float s = c[0][ni][j] + c[0][ni][j + 2] + c[1][ni][j] + c[1][ni][j + 2];
            float q = c[0][ni][j]     * c[0][ni][j]
                    + c[0][ni][j + 2] * c[0][ni][j + 2]
                    + c[1][ni][j]     * c[1][ni][j]
                    + c[1][ni][j + 2] * c[1][ni][j + 2];
#pragma unroll
            for (int m = 16; m >= 4; m >>= 1) {
                s += __shfl_xor_sync(0xffffffffu, s, m);
                q += __shfl_xor_sync(0xffffffffu, q, m);
            }
            if (lane < 4) {
                int cch = warpCol * 64 + ni * 8 + tg * 2 + j;
                atomicAdd(&ssum[cch], s);
                atomicAdd(&ssq [cch], q);
            }
        }
    }
    __syncthreads();
    if (tid < 128) {
        atomicAdd(&d_sum  [256 + tid], ssum[tid]);
        atomicAdd(&d_sumsq[256 + tid], ssq[tid]);
    }
}

// ---------------------------------------------------------------------------
// Gram kernel (single-buffer, R14 config): G = X2^T X2, xsum = sum_rows X2.
// ---------------------------------------------------------------------------
__global__ void __launch_bounds__(256, 2) gram_kernel(
    const float* __restrict__ g, const float* __restrict__ b) {
    __shared__ uint32_t As[128 * KW];
    __shared__ float scs[128], shs[128], ssum[128];

    const int tid = threadIdx.x;
    const int wid = tid >> 5;
    const int lane = tid & 31;
    const int gid = lane >> 2;
    const int tg  = lane & 3;
    const int warpRow = wid & 3;
    const int warpCol = wid >> 2;
    const int t8 = lane >> 3, r8 = lane & 7;
    const int cw = tid & 15;

    if (tid < 128) {
        float mean = d_sum[256 + tid] * (1.0f / (float)ROWS);
        float var  = d_sumsq[256 + tid] * (1.0f / (float)ROWS) - mean * mean;
        float sc = g[tid] * rsqrtf(var + BN_EPS);
        scs[tid] = sc;
        shs[tid] = b[tid] - mean * sc;
        ssum[tid] = 0.f;
    }
    __syncthreads();

    uint32_t base = smem_u32(As);
    uint32_t aT[2], bT[4];
#pragma unroll
    for (int mi = 0; mi < 2; mi++) {
        int mbase = warpRow * 32 + mi * 16 + (t8 & 1) * 8;
        aT[mi] = base + (uint32_t)(((t8 >> 1) * 8 + r8) * KW4) + (uint32_t)(mbase * 2);
    }
#pragma unroll
    for (int nj = 0; nj < 4; nj++) {
        int nbase = warpCol * 64 + nj * 16 + (t8 >> 1) * 8;
        bT[nj] = base + (uint32_t)(((t8 & 1) * 8 + r8) * KW4) + (uint32_t)(nbase * 2);
    }

    float c[2][8][4];
#pragma unroll
    for (int mi = 0; mi < 2; mi++)
#pragma unroll
        for (int ni = 0; ni < 8; ni++)
#pragma unroll
            for (int j = 0; j < 4; j++) c[mi][ni][j] = 0.f;
    float xs[8];
#pragma unroll
    for (int j = 0; j < 8; j++) xs[j] = 0.f;

    for (int t = 0; t < 16; t++) {
        int rowBase = blockIdx.x * 2048 + t * 128;
#pragma unroll
        for (int i = 0; i < 8; i++) {
            int e = tid + i * 256;
            int r = e >> 4;
            uint4 h = ((const uint4*)&d_y1[(size_t)(rowBase + r) * 128])[cw];
            uint32_t hw[4] = {h.x, h.y, h.z, h.w};
            const float* sc = &scs[cw * 8];
            const float* sh = &shs[cw * 8];
            float y[8];
#pragma unroll
            for (int j = 0; j < 4; j++) {
                float2 f = __half22float2(*(__half2*)&hw[j]);
                y[j * 2]     = lrelu(f.x * sc[j * 2]     + sh[j * 2]);
                y[j * 2 + 1] = lrelu(f.y * sc[j * 2 + 1] + sh[j * 2 + 1]);
            }
            uint4 v;
            v.x = pack_h2(y[0], y[1]); v.y = pack_h2(y[2], y[3]);
            v.z = pack_h2(y[4], y[5]); v.w = pack_h2(y[6], y[7]);
            uint32_t vv[4] = {v.x, v.y, v.z, v.w};
#pragma unroll
            for (int j = 0; j < 4; j++) {
                float2 f = __half22float2(*(__half2*)&vv[j]);
                xs[j * 2] += f.x; xs[j * 2 + 1] += f.y;
            }
            *(uint4*)&As[r * KW + cw * 4] = v;
        }
        __syncthreads();
#pragma unroll
        for (int k0 = 0; k0 < 8; k0++) {
            uint32_t off = (uint32_t)(k0 * 16 * KW4);
            uint32_t af[2][4], bf[4][4];
#pragma unroll
            for (int mi = 0; mi < 2; mi++) ldmatrix_x4_trans(af[mi], aT[mi] + off);
#pragma unroll
            for (int nj = 0; nj < 4; nj++) ldmatrix_x4_trans(bf[nj], bT[nj] + off);
#pragma unroll
            for (int mi = 0; mi < 2; mi++)
#pragma unroll
                for (int nj = 0; nj < 4; nj++) {
                    mma_f16(c[mi][nj * 2],     af[mi], &bf[nj][0]);
                    mma_f16(c[mi][nj * 2 + 1], af[mi], &bf[nj][2]);
                }
        }
        __syncthreads();
    }

#pragma unroll
    for (int mi = 0; mi < 2; mi++) {
        int m0 = warpRow * 32 + mi * 16 + gid;
#pragma unroll
        for (int ni = 0; ni < 8; ni++) {
            int n0 = warpCol * 64 + ni * 8 + tg * 2;
            atomicAdd(&d_gram[ m0      * 128 + n0    ], c[mi][ni][0]);
            atomicAdd(&d_gram[ m0      * 128 + n0 + 1], c[mi][ni][1]);
            atomicAdd(&d_gram[(m0 + 8) * 128 + n0    ], c[mi][ni][2]);
            atomicAdd(&d_gram[(m0 + 8) * 128 + n0 + 1], c[mi][ni][3]);
        }
    }
#pragma unroll
    for (int j = 0; j < 8; j++) atomicAdd(&ssum[cw * 8 + j], xs[j]);
    __syncthreads();
    if (tid < 128) atomicAdd(&d_xsum[tid], ssum[tid]);
}

// ---------------------------------------------------------------------------
// BN2 prep: per channel c, sum = xsum.w_c ; sumsq = w_c^T G w_c.
// ---------------------------------------------------------------------------
__global__ void __launch_bounds__(128) bn2_prep_kernel() {
    const int c = blockIdx.x;
    const int tid = threadIdx.x;
    __shared__ float w[128];
    __shared__ float red[8];
    if (tid < 64) {
        uint32_t p = d_W2t[c * 64 + tid];
        float2 f = __half22float2(*(__half2*)&p);
        w[2 * tid] = f.x; w[2 * tid + 1] = f.y;
    }
    __syncthreads();
    float wj = w[tid];
    float v = 0.f;
#pragma unroll 8
    for (int i = 0; i < 128; i++) v += w[i] * d_gram[i * 128 + tid];
    float q = wj * v;
    float s = wj * d_xsum[tid];
#pragma unroll
    for (int m = 16; m >= 1; m >>= 1) {
        q += __shfl_xor_sync(0xffffffffu, q, m);
        s += __shfl_xor_sync(0xffffffffu, s, m);
    }
    if ((tid & 31) == 0) { red[(tid >> 5) * 2] = q; red[(tid >> 5) * 2 + 1] = s; }
    __syncthreads();
    if (tid == 0) {
        d_sumsq[512 + c] = red[0] + red[2] + red[4] + red[6];
        d_sum  [512 + c] = red[1] + red[3] + red[5] + red[7];
    }
}

// ---------------------------------------------------------------------------
// Layer-2 MMA + fused k-mean + shortcut + final lrelu -> out (no y2).
// ---------------------------------------------------------------------------
__global__ void __launch_bounds__(256, 2) mma2_out_kernel(
    const float* __restrict__ g1, const float* __restrict__ b1,
    const float* __restrict__ g2, const float* __restrict__ b2,
    const float* __restrict__ gsc, const float* __restrict__ bsc,
    float* __restrict__ out) {
    extern __shared__ char smem_raw[];
    uint32_t* As = (uint32_t*)smem_raw;                    // [128][KW]
    uint32_t* Bs = As + 128 * KW;                          // [128][KW]
    float* fts = (float*)(Bs + 128 * KW);                  // [8][256]
    float* scs = fts + 8 * 256;                            // [128]
    float* shs = scs + 128;                                // [128]
    float* s2s = shs + 128;                                // [256]
    float* h2s = s2s + 256;                                // [256]
    float* s3s = h2s + 256;                                // [256]
    float* h3s = s3s + 256;                                // [256]

    const int tid = threadIdx.x;
    const int wid = tid >> 5;
    const int lane = tid & 31;
    const int tg  = lane & 3;
    const int warpRow = wid & 3;
    const int warpCol = wid >> 2;
    const int tileBase = blockIdx.x * 128;

    if (tid < 128) {
        float mean = d_sum[256 + tid] * (1.0f / (float)ROWS);
        float var  = d_sumsq[256 + tid] * (1.0f / (float)ROWS) - mean * mean;
        float sc = g1[tid] * rsqrtf(var + BN_EPS);
        scs[tid] = sc;
        shs[tid] = b1[tid] - mean * sc;
    }
    {
        int cch = tid;
        float mean2 = d_sum[512 + cch] * (1.0f / (float)ROWS);
        float var2  = d_sumsq[512 + cch] * (1.0f / (float)ROWS) - mean2 * mean2;
        float sc2 = g2[cch] * rsqrtf(var2 + BN_EPS);
        s2s[cch] = sc2; h2s[cch] = b2[cch] - mean2 * sc2;
        float mean3 = d_sum[768 + cch] * (1.0f / (float)NPTS);
        float var3  = d_sumsq[768 + cch] * (1.0f / (float)NPTS) - mean3 * mean3;
        float sc3 = gsc[cch] * rsqrtf(var3 + BN_EPS);
        s3s[cch] = sc3; h3s[cch] = bsc[cch] - mean3 * sc3;
    }
    __syncthreads();

#pragma unroll
    for (int i = 0; i < 8; i++) {
        int e = tid + i * 256;
        int r = e >> 4, cw = e & 15;
        uint4 h = ((const uint4*)&d_y1[(size_t)(tileBase + r) * 128])[cw];
        uint32_t hw[4] = {h.x, h.y, h.z, h.w};
        const float* sc = &scs[cw * 8];
        const float* sh = &shs[cw * 8];
        float y[8];
#pragma unroll
        for (int j = 0; j < 4; j++) {
            float2 f = __half22float2(*(__half2*)&hw[j]);
            y[j * 2]     = lrelu(f.x * sc[j * 2]     + sh[j * 2]);
            y[j * 2 + 1] = lrelu(f.y * sc[j * 2 + 1] + sh[j * 2 + 1]);
        }
        uint4 v;
        v.x = pack_h2(y[0], y[1]); v.y = pack_h2(y[2], y[3]);
        v.z = pack_h2(y[4], y[5]); v.w = pack_h2(y[6], y[7]);
        *(uint4*)&As[r * KW + cw * 4] = v;
    }
    {
        const uint4* src = (const uint4*)d_W2t;
#pragma unroll
        for (int i = 0; i < 8; i++) {
            int e4 = tid + i * 256;
            int n = e4 >> 4, kw4 = e4 & 15;
            *(uint4*)&Bs[n * KW + kw4 * 4] = src[e4];
        }
    }
    __syncthreads();

    const int t8 = lane >> 3, r8 = lane & 7;
    uint32_t aAddr[2], bAddr[4];
#pragma unroll
    for (int mi = 0; mi < 2; mi++) {
        int row = warpRow * 32 + mi * 16 + (t8 & 1) * 8 + r8;
        aAddr[mi] = smem_u32(&As[row * KW + (t8 >> 1) * 4]);
    }
#pragma unroll
    for (int nj = 0; nj < 4; nj++) {
        int row = warpCol * 64 + nj * 16 + (t8 >> 1) * 8 + r8;
        bAddr[nj] = smem_u32(&Bs[row * KW + (t8 & 1) * 4]);
    }

#pragma unroll
    for (int h = 0; h < 2; h++) {
        if (h == 1) {
            __syncthreads();
            const uint4* src = (const uint4*)d_W2t + 2048;
#pragma unroll
            for (int i = 0; i < 8; i++) {
                int e4 = tid + i * 256;
                int n = e4 >> 4, kw4 = e4 & 15;
                *(uint4*)&Bs[n * KW + kw4 * 4] = src[e4];
            }
            __syncthreads();
        }
        float c[2][8][4];
#pragma unroll
        for (int mi = 0; mi < 2; mi++)
#pragma unroll
            for (int ni = 0; ni < 8; ni++)
#pragma unroll
                for (int j = 0; j < 4; j++) c[mi][ni][j] = 0.f;
#pragma unroll
        for (int k0 = 0; k0 < 8; k0++) {
            uint32_t af[2][4], bf[4][4];
#pragma unroll
            for (int mi = 0; mi < 2; mi++) ldmatrix_x4(af[mi], aAddr[mi] + k0 * 32);
#pragma unroll
            for (int nj = 0; nj < 4; nj++) ldmatrix_x4(bf[nj], bAddr[nj] + k0 * 32);
#pragma unroll
            for (int mi = 0; mi < 2; mi++)
#pragma unroll
                for (int nj = 0; nj < 4; nj++) {
                    mma_f16(c[mi][nj * 2],     af[mi], &bf[nj][0]);
                    mma_f16(c[mi][nj * 2 + 1], af[mi], &bf[nj][2]);
                }
        }
#pragma unroll
        for (int mi = 0; mi < 2; mi++) {
            int npL = warpRow * 2 + mi;
#pragma unroll
            for (int ni = 0; ni < 8; ni++) {
#pragma unroll
                for (int j = 0; j < 2; j++) {
                    int cch = h * 128 + warpCol * 64 + ni * 8 + tg * 2 + j;
                    float sv = s2s[cch], hv = h2s[cch];
                    float p = lrelu(c[mi][ni][j] * sv + hv)
                            + lrelu(c[mi][ni][j + 2] * sv + hv);
#pragma unroll
                    for (int m = 16; m >= 4; m >>= 1)
                        p += __shfl_xor_sync(0xffffffffu, p, m);
                    if (lane < 4) fts[npL * 256 + cch] = p;
                }
            }
        }
    }
    __syncthreads();

    const int npBase = blockIdx.x * 8;
#pragma unroll
    for (int i = 0; i < 2; i++) {
        int e4 = tid + i * 256;
        int npL = e4 >> 6, c4 = e4 & 63;
        float4 sc = ((const float4*)d_SC)[(size_t)(npBase + npL) * 64 + c4];
        float4 f  = ((const float4*)fts)[npL * 64 + c4];
        const float inv = 1.0f / 16.0f;
        float4 o;
        o.x = lrelu(sc.x * s3s[c4 * 4 + 0] + h3s[c4 * 4 + 0] + f.x * inv);
        o.y = lrelu(sc.y * s3s[c4 * 4 + 1] + h3s[c4 * 4 + 1] + f.y * inv);
        o.z = lrelu(sc.z * s3s[c4 * 4 + 2] + h3s[c4 * 4 + 2] + f.z * inv);
        o.w = lrelu(sc.w * s3s[c4 * 4 + 3] + h3s[c4 * 4 + 3] + f.w * inv);
        ((float4*)out)[(size_t)(npBase + npL) * 64 + c4] = o;
    }
}

// ---------------------------------------------------------------------------
// Launch (6 launches; gram at idx 3 -> ncu abs index 5)
// ---------------------------------------------------------------------------
extern "C" void kernel_launch(void* const* d_in, const int* in_sizes, int n_in,
                              void* d_out, int out_size) {
    const float* points   = (const float*)d_in[0];
    const float* features = (const float*)d_in[1];
    const float* W0  = (const float*)d_in[2];
    const float* g0  = (const float*)d_in[3];
    const float* b0  = (const float*)d_in[4];
    const float* W1  = (const float*)d_in[5];
    const float* g1  = (const float*)d_in[6];
    const float* b1  = (const float*)d_in[7];
    const float* W2  = (const float*)d_in[8];
    const float* g2  = (const float*)d_in[9];
    const float* b2  = (const float*)d_in[10];
    const float* Wsc = (const float*)d_in[11];
    const float* gsc = (const float*)d_in[12];
    const float* bsc = (const float*)d_in[13];
    float* out = (float*)d_out;

    __half* p1;
    uint32_t* pW1t;
    cudaGetSymbolAddress((void**)&p1,  d_y1);
    cudaGetSymbolAddress((void**)&pW1t, d_W1t);

    constexpr int SMEM_MEGA = (128 * KW2 + 256 * KW2) * 4;        // 55296
    constexpr int SMEM_MMA1 = (2 * 128 * KW) * 4 + 4 * 128 * 4;
    constexpr int SMEM_OUT  = (2 * 128 * KW) * 4 + 8 * 256 * 4 + (2 * 128 + 4 * 256) * 4;
    cudaFuncSetAttribute(mega_kernel,
                         cudaFuncAttributeMaxDynamicSharedMemorySize, SMEM_MEGA);
    cudaFuncSetAttribute(gemm_mma1_kernel,
                         cudaFuncAttributeMaxDynamicSharedMemorySize, SMEM_MMA1);
    cudaFuncSetAttribute(mma2_out_kernel,
                         cudaFuncAttributeMaxDynamicSharedMemorySize, SMEM_OUT);

    // 0: mega setup (knn + side duties + tensor dual/SC GEMMs)
    mega_kernel<<<640, 256, SMEM_MEGA>>>(points, features, W0, Wsc, W1, W2);
    // 1: layer-0 virtual-y0 stats + SC stats
    stats_kernel<<<2560, 256>>>();
    // 2: layer-1 MMA -> y1 + BN1 stats
    gemm_mma1_kernel<<<ROWS / 128, 256, SMEM_MMA1>>>(pW1t, p1, g0, b0);
    // 3: Gram of x2 + xsum (tensor syrk, single-buffer)  [PROFILED]
    gram_kernel<<<256, 256>>>(g1, b1);
    // 4: BN2 stats from Gram
    bn2_prep_kernel<<<256, 128>>>();
    // 5: layer-2 MMA + k-mean + shortcut + out
    mma2_out_kernel<<<ROWS / 128, 256, SMEM_OUT>>>(g1, b1, g2, b2, gsc, bsc, out);
}